// round 3
// baseline (speedup 1.0000x reference)
#include <cuda_runtime.h>
#include <math.h>

// ---------------------------------------------------------------------------
// Problem constants: B=4, N=2048, D=1024, GROUPS=4
// ---------------------------------------------------------------------------
#define BM 128
#define BN 128
#define BK 16
#define APITCH 264   // duplicated A: 256 floats + pad
#define BPITCH 132   // 128 floats + pad

// Scratch (static device allocations are allowed; cudaMalloc is not)
__device__ float g_q  [8388608];   // [4,2048,1024]
__device__ float g_k  [8388608];
__device__ float g_v  [8388608];
__device__ float g_att[16777216];  // [4,2048,2048]
__device__ float g_mix[8388608];   // att_out, then att_out+conv
__device__ float g_gl [8388608];   // res-gate logits
__device__ float g_ln [8388608];   // layernorm output
__device__ float g_h  [4194304];   // [8192,512]
__device__ float g_wt [786432];    // conv_w transposed: [3][1024][256]

// ---------------------------------------------------------------------------
// Packed fp32 helpers (Blackwell f32x2 — 2x fp32 FMA per instruction)
// ---------------------------------------------------------------------------
__device__ __forceinline__ void ffma2(unsigned long long &c,
                                      unsigned long long a,
                                      unsigned long long b) {
    asm("fma.rn.f32x2 %0, %1, %2, %0;" : "+l"(c) : "l"(a), "l"(b));
}
__device__ __forceinline__ float2 unpk(unsigned long long v) {
    unsigned lo, hi;
    asm("mov.b64 {%0,%1}, %2;" : "=r"(lo), "=r"(hi) : "l"(v));
    float2 r; r.x = __uint_as_float(lo); r.y = __uint_as_float(hi);
    return r;
}

// One k-step of the 8x8 microtile via FFMA2. A comes pre-duplicated from SMEM
// (pairs (a,a)); B pairs (b0,b1) are natural from consecutive floats.
__device__ __forceinline__ void gemm_step(const float (&As2)[BK][APITCH],
                                          const float (&Bs)[BK][BPITCH],
                                          int k, unsigned long long (&acc2)[8][4],
                                          int ty, int tx) {
    const ulonglong2* pa = (const ulonglong2*)&As2[k][ty * 16];
    const ulonglong2* pb = (const ulonglong2*)&Bs[k][tx * 8];
    ulonglong2 a01 = pa[0], a23 = pa[1], a45 = pa[2], a67 = pa[3];
    ulonglong2 b03 = pb[0], b47 = pb[1];
    unsigned long long aa[8] = {a01.x, a01.y, a23.x, a23.y,
                                a45.x, a45.y, a67.x, a67.y};
    unsigned long long bb[4] = {b03.x, b03.y, b47.x, b47.y};
    #pragma unroll
    for (int i = 0; i < 8; i++) {
        #pragma unroll
        for (int j = 0; j < 4; j++) ffma2(acc2[i][j], aa[i], bb[j]);
    }
}

// ---------------------------------------------------------------------------
// NT GEMM: C[m,n] = sum_k A[m,k]*B[n,k]   (A:[M,K], B:[N,K], row-major)
// MODE 0: plain     (q/k/v, res-gate)
// MODE 1: scores    (batched; C = acc*scale + rel_bias[m,n]; skip upper tiles)
// MODE 2: fc1       (C = gelu_exact(acc + bias[n]))
// ---------------------------------------------------------------------------
template<int MODE>
__global__ void __launch_bounds__(256)
gemm_nt(const float* __restrict__ A, const float* __restrict__ B,
        float* __restrict__ C, int M, int N, int K,
        const float* __restrict__ bias, float scale,
        long long sA, long long sB, long long sC) {
    int m0 = blockIdx.y * BM;
    int n0 = blockIdx.x * BN;
    if (MODE == 1 && n0 > m0) return;   // strictly-above-diagonal tile: never read
    A += (long long)blockIdx.z * sA;
    B += (long long)blockIdx.z * sB;
    C += (long long)blockIdx.z * sC;

    __shared__ float As2[BK][APITCH];
    __shared__ float Bs [BK][BPITCH];

    int tid = threadIdx.x;
    int tx = tid & 15, ty = tid >> 4;
    unsigned long long acc2[8][4];
    #pragma unroll
    for (int i = 0; i < 8; i++)
        #pragma unroll
        for (int j = 0; j < 4; j++) acc2[i][j] = 0ull;

    const float* Ab = A + (long long)m0 * K;
    const float* Bb = B + (long long)n0 * K;

    for (int k0 = 0; k0 < K; k0 += BK) {
        #pragma unroll
        for (int h = 0; h < 2; h++) {
            int idx = tid + h * 256;
            int r = idx >> 2;
            int c = (idx & 3) * 4;
            float4 va = *(const float4*)(Ab + (long long)r * K + k0 + c);
            float2 d;
            d.x = d.y = va.x; *(float2*)&As2[c + 0][2 * r] = d;
            d.x = d.y = va.y; *(float2*)&As2[c + 1][2 * r] = d;
            d.x = d.y = va.z; *(float2*)&As2[c + 2][2 * r] = d;
            d.x = d.y = va.w; *(float2*)&As2[c + 3][2 * r] = d;
            float4 vb = *(const float4*)(Bb + (long long)r * K + k0 + c);
            Bs[c + 0][r] = vb.x; Bs[c + 1][r] = vb.y;
            Bs[c + 2][r] = vb.z; Bs[c + 3][r] = vb.w;
        }
        __syncthreads();
        #pragma unroll
        for (int k = 0; k < BK; k++) gemm_step(As2, Bs, k, acc2, ty, tx);
        __syncthreads();
    }

    int ncol = n0 + tx * 8;
    #pragma unroll
    for (int i = 0; i < 8; i++) {
        int m = m0 + ty * 8 + i;
        float o[8];
        #pragma unroll
        for (int j = 0; j < 4; j++) {
            float2 u = unpk(acc2[i][j]);
            o[2 * j] = u.x; o[2 * j + 1] = u.y;
        }
        if (MODE == 1) {
            const float* bp = bias + (long long)m * 2048 + ncol;
            #pragma unroll
            for (int j = 0; j < 8; j++) o[j] = o[j] * scale + bp[j];
        } else if (MODE == 2) {
            #pragma unroll
            for (int j = 0; j < 8; j++) {
                float z = o[j] + bias[ncol + j];
                o[j] = 0.5f * z * (1.0f + erff(z * 0.70710678118654752f));
            }
        }
        float* cp = C + (long long)m * N + ncol;
        *(float4*)cp       = make_float4(o[0], o[1], o[2], o[3]);
        *(float4*)(cp + 4) = make_float4(o[4], o[5], o[6], o[7]);
    }
}

// ---------------------------------------------------------------------------
// NN GEMM with causal K-bound: att_out = P @ V (batched).
// P rows in tile [m0,m0+127] only have defined entries for k < m0+128.
// ---------------------------------------------------------------------------
__global__ void __launch_bounds__(256)
gemm_nn_causal(const float* __restrict__ A, const float* __restrict__ B,
               float* __restrict__ C, int M, int N, int K) {
    int m0 = blockIdx.y * BM;
    int n0 = blockIdx.x * BN;
    A += (long long)blockIdx.z * M * K;
    B += (long long)blockIdx.z * K * N;
    C += (long long)blockIdx.z * M * N;
    int Keff = m0 + BM;   // causal bound (<= K)

    __shared__ float As2[BK][APITCH];
    __shared__ float Bs [BK][BPITCH];

    int tid = threadIdx.x;
    int tx = tid & 15, ty = tid >> 4;
    unsigned long long acc2[8][4];
    #pragma unroll
    for (int i = 0; i < 8; i++)
        #pragma unroll
        for (int j = 0; j < 4; j++) acc2[i][j] = 0ull;

    const float* Ab = A + (long long)m0 * K;

    for (int k0 = 0; k0 < Keff; k0 += BK) {
        #pragma unroll
        for (int h = 0; h < 2; h++) {
            int idx = tid + h * 256;
            int r = idx >> 2;
            int c = (idx & 3) * 4;
            float4 va = *(const float4*)(Ab + (long long)r * K + k0 + c);
            float2 d;
            d.x = d.y = va.x; *(float2*)&As2[c + 0][2 * r] = d;
            d.x = d.y = va.y; *(float2*)&As2[c + 1][2 * r] = d;
            d.x = d.y = va.z; *(float2*)&As2[c + 2][2 * r] = d;
            d.x = d.y = va.w; *(float2*)&As2[c + 3][2 * r] = d;
            // B tile: rows along K, cols along N (direct, coalesced)
            int kk = idx >> 5;
            int cc = (idx & 31) * 4;
            float4 vb = *(const float4*)(B + (long long)(k0 + kk) * N + n0 + cc);
            *(float4*)&Bs[kk][cc] = vb;
        }
        __syncthreads();
        #pragma unroll
        for (int k = 0; k < BK; k++) gemm_step(As2, Bs, k, acc2, ty, tx);
        __syncthreads();
    }

    int ncol = n0 + tx * 8;
    #pragma unroll
    for (int i = 0; i < 8; i++) {
        int m = m0 + ty * 8 + i;
        float o[8];
        #pragma unroll
        for (int j = 0; j < 4; j++) {
            float2 u = unpk(acc2[i][j]);
            o[2 * j] = u.x; o[2 * j + 1] = u.y;
        }
        float* cp = C + (long long)m * N + ncol;
        *(float4*)cp       = make_float4(o[0], o[1], o[2], o[3]);
        *(float4*)(cp + 4) = make_float4(o[4], o[5], o[6], o[7]);
    }
}

// ---------------------------------------------------------------------------
// Grouped temporal conv as a K=768 NT GEMM over (tap,ci).
// A virtual: A[t,k] = V[b, t+tap-1, g*256+ci] (zero-padded at t edges)
// B: wt[tap][co][ci] (pre-transposed conv_w -> contiguous loads)
// Epilogue: mix[b,t,co] += acc + conv_b[co]   (mix already holds att_out)
// ---------------------------------------------------------------------------
__global__ void __launch_bounds__(256)
conv_mix_kernel(const float* __restrict__ V, const float* __restrict__ WT,
                const float* __restrict__ cb, float* __restrict__ mix) {
    int b  = blockIdx.z;
    int n0 = blockIdx.x * BN;   // c_out tile (8 tiles -> groups of 2 per group)
    int m0 = blockIdx.y * BM;   // t tile
    int g  = n0 >> 8;           // group (128 | 256, so constant per tile)
    const float* vb = V + (long long)b * 2048 * 1024 + g * 256;

    __shared__ float As2[BK][APITCH];
    __shared__ float Bs [BK][BPITCH];

    int tid = threadIdx.x;
    int tx = tid & 15, ty = tid >> 4;
    unsigned long long acc2[8][4];
    #pragma unroll
    for (int i = 0; i < 8; i++)
        #pragma unroll
        for (int j = 0; j < 4; j++) acc2[i][j] = 0ull;

    for (int k0 = 0; k0 < 768; k0 += BK) {
        #pragma unroll
        for (int h = 0; h < 2; h++) {
            int idx = tid + h * 256;
            int r = idx >> 2;
            int c = (idx & 3) * 4;
            int kg  = k0 + c;          // global k; whole float4 in one tap
            int tap = kg >> 8;
            int ci  = kg & 255;
            int row = m0 + r + tap - 1;
            float4 va = make_float4(0.f, 0.f, 0.f, 0.f);
            if (row >= 0 && row < 2048)
                va = *(const float4*)(vb + (long long)row * 1024 + ci);
            float2 d;
            d.x = d.y = va.x; *(float2*)&As2[c + 0][2 * r] = d;
            d.x = d.y = va.y; *(float2*)&As2[c + 1][2 * r] = d;
            d.x = d.y = va.z; *(float2*)&As2[c + 2][2 * r] = d;
            d.x = d.y = va.w; *(float2*)&As2[c + 3][2 * r] = d;
            float4 w4 = *(const float4*)(WT + (long long)tap * 262144
                                            + (long long)(n0 + r) * 256 + ci);
            Bs[c + 0][r] = w4.x; Bs[c + 1][r] = w4.y;
            Bs[c + 2][r] = w4.z; Bs[c + 3][r] = w4.w;
        }
        __syncthreads();
        #pragma unroll
        for (int k = 0; k < BK; k++) gemm_step(As2, Bs, k, acc2, ty, tx);
        __syncthreads();
    }

    int ncol = n0 + tx * 8;
    #pragma unroll
    for (int i = 0; i < 8; i++) {
        int m = m0 + ty * 8 + i;
        float o[8];
        #pragma unroll
        for (int j = 0; j < 4; j++) {
            float2 u = unpk(acc2[i][j]);
            o[2 * j] = u.x; o[2 * j + 1] = u.y;
        }
        float* dst = mix + ((long long)b * 2048 + m) * 1024 + ncol;
        float4 p0 = *(float4*)dst;
        float4 p1 = *(float4*)(dst + 4);
        p0.x += o[0] + cb[ncol + 0]; p0.y += o[1] + cb[ncol + 1];
        p0.z += o[2] + cb[ncol + 2]; p0.w += o[3] + cb[ncol + 3];
        p1.x += o[4] + cb[ncol + 4]; p1.y += o[5] + cb[ncol + 5];
        p1.z += o[6] + cb[ncol + 6]; p1.w += o[7] + cb[ncol + 7];
        *(float4*)dst       = p0;
        *(float4*)(dst + 4) = p1;
    }
}

// conv_w [co][ci][tap] -> wt [tap][co][ci]
__global__ void transpose_w_kernel(const float* __restrict__ cw,
                                   float* __restrict__ wt) {
    int i = blockIdx.x * blockDim.x + threadIdx.x;
    if (i < 262144) {
        int co = i >> 8, ci = i & 255;
        const float* src = cw + (long long)co * 768 + ci * 3;
        wt[i]              = src[0];
        wt[262144 + i]     = src[1];
        wt[2 * 262144 + i] = src[2];
    }
}

// ---------------------------------------------------------------------------
// Causal softmax, in place. Row i: valid cols [0, i], writes zeros to the
// 128-aligned pad so the PV GEMM can read dense tiles.
// ---------------------------------------------------------------------------
__global__ void softmax_rows(float* __restrict__ att) {
    int row = blockIdx.x;
    int b = row >> 11;
    int i = row & 2047;
    int L = i + 1;
    int Lpad = ((i >> 7) + 1) << 7;
    float* s = att + ((long long)b * 2048 + i) * 2048;
    int tid = threadIdx.x;

    float v[8];
    float m = -3.0e38f;
    #pragma unroll
    for (int r = 0; r < 8; r++) {
        int j = r * 256 + tid;
        v[r] = (j < L) ? s[j] : -3.0e38f;
        m = fmaxf(m, v[r]);
    }
    __shared__ float red[256];
    red[tid] = m; __syncthreads();
    #pragma unroll
    for (int o = 128; o > 0; o >>= 1) {
        if (tid < o) red[tid] = fmaxf(red[tid], red[tid + o]);
        __syncthreads();
    }
    m = red[0]; __syncthreads();

    float sum = 0.f;
    #pragma unroll
    for (int r = 0; r < 8; r++) { v[r] = __expf(v[r] - m); sum += v[r]; }
    red[tid] = sum; __syncthreads();
    #pragma unroll
    for (int o = 128; o > 0; o >>= 1) {
        if (tid < o) red[tid] += red[tid + o];
        __syncthreads();
    }
    float inv = 1.0f / red[0];
    #pragma unroll
    for (int r = 0; r < 8; r++) {
        int j = r * 256 + tid;
        if (j < Lpad) s[j] = v[r] * inv;   // masked pad entries are exp(-inf)=0
    }
}

// ---------------------------------------------------------------------------
// Fused: t = x + sigmoid(gl + resg_b) * mix ; LayerNorm(t) -> out
// ---------------------------------------------------------------------------
__global__ void fuse_res_ln(const float* __restrict__ x,
                            const float* __restrict__ gl,
                            const float* __restrict__ mix,
                            const float* __restrict__ rb,
                            const float* __restrict__ lg,
                            const float* __restrict__ lb,
                            float* __restrict__ outp) {
    int row = blockIdx.x;
    int tid = threadIdx.x;
    int c = tid * 4;
    long long base = (long long)row * 1024 + c;
    float4 xv = *(const float4*)(x + base);
    float4 gv = *(const float4*)(gl + base);
    float4 mv = *(const float4*)(mix + base);
    float4 bv = *(const float4*)(rb + c);
    float t0 = xv.x + mv.x / (1.f + __expf(-(gv.x + bv.x)));
    float t1 = xv.y + mv.y / (1.f + __expf(-(gv.y + bv.y)));
    float t2 = xv.z + mv.z / (1.f + __expf(-(gv.z + bv.z)));
    float t3 = xv.w + mv.w / (1.f + __expf(-(gv.w + bv.w)));

    float s  = t0 + t1 + t2 + t3;
    float ss = t0 * t0 + t1 * t1 + t2 * t2 + t3 * t3;
    __shared__ float r1[256], r2[256];
    r1[tid] = s; r2[tid] = ss; __syncthreads();
    #pragma unroll
    for (int o = 128; o > 0; o >>= 1) {
        if (tid < o) { r1[tid] += r1[tid + o]; r2[tid] += r2[tid + o]; }
        __syncthreads();
    }
    float mu  = r1[0] * (1.0f / 1024.0f);
    float var = r2[0] * (1.0f / 1024.0f) - mu * mu;
    float inv = rsqrtf(var + 1e-5f);
    float4 gw = *(const float4*)(lg + c);
    float4 bw = *(const float4*)(lb + c);
    float4 o4;
    o4.x = (t0 - mu) * inv * gw.x + bw.x;
    o4.y = (t1 - mu) * inv * gw.y + bw.y;
    o4.z = (t2 - mu) * inv * gw.z + bw.z;
    o4.w = (t3 - mu) * inv * gw.w + bw.w;
    *(float4*)(outp + base) = o4;
}

// out[row] = sigmoid(dot(h[row], fc2_w) + fc2_b)  — one warp per row
__global__ void fc2_sigmoid(const float* __restrict__ h,
                            const float* __restrict__ w,
                            const float* __restrict__ b,
                            float* __restrict__ out) {
    int warp = (blockIdx.x * blockDim.x + threadIdx.x) >> 5;
    int lane = threadIdx.x & 31;
    const float* hr = h + (long long)warp * 512;
    float s = 0.f;
    #pragma unroll
    for (int j = 0; j < 512; j += 32) s += hr[j + lane] * w[j + lane];
    #pragma unroll
    for (int o = 16; o > 0; o >>= 1) s += __shfl_down_sync(0xffffffffu, s, o);
    if (lane == 0) out[warp] = 1.0f / (1.0f + __expf(-(s + b[0])));
}

// ---------------------------------------------------------------------------
extern "C" void kernel_launch(void* const* d_in, const int* in_sizes, int n_in,
                              void* d_out, int out_size) {
    const float* x        = (const float*)d_in[0];
    const float* Wq       = (const float*)d_in[1];
    const float* Wk       = (const float*)d_in[2];
    const float* Wv       = (const float*)d_in[3];
    const float* rel_bias = (const float*)d_in[4];
    const float* conv_w   = (const float*)d_in[5];
    const float* conv_b   = (const float*)d_in[6];
    const float* resg_w   = (const float*)d_in[7];
    const float* resg_b   = (const float*)d_in[8];
    const float* ln_g     = (const float*)d_in[9];
    const float* ln_b     = (const float*)d_in[10];
    const float* fc1_w    = (const float*)d_in[11];
    const float* fc1_b    = (const float*)d_in[12];
    const float* fc2_w    = (const float*)d_in[13];
    const float* fc2_b    = (const float*)d_in[14];
    float* out = (float*)d_out;

    float *q, *k, *v, *att, *mix, *gl, *ln, *h, *wt;
    cudaGetSymbolAddress((void**)&q,   g_q);
    cudaGetSymbolAddress((void**)&k,   g_k);
    cudaGetSymbolAddress((void**)&v,   g_v);
    cudaGetSymbolAddress((void**)&att, g_att);
    cudaGetSymbolAddress((void**)&mix, g_mix);
    cudaGetSymbolAddress((void**)&gl,  g_gl);
    cudaGetSymbolAddress((void**)&ln,  g_ln);
    cudaGetSymbolAddress((void**)&h,   g_h);
    cudaGetSymbolAddress((void**)&wt,  g_wt);

    // conv weight relayout (tiny, runs concurrently with nothing it conflicts with)
    transpose_w_kernel<<<1024, 256>>>(conv_w, wt);

    // q, k, v projections
    gemm_nt<0><<<dim3(8, 64, 1), 256>>>(x, Wq, q, 8192, 1024, 1024, nullptr, 1.f, 0, 0, 0);
    gemm_nt<0><<<dim3(8, 64, 1), 256>>>(x, Wk, k, 8192, 1024, 1024, nullptr, 1.f, 0, 0, 0);
    gemm_nt<0><<<dim3(8, 64, 1), 256>>>(x, Wv, v, 8192, 1024, 1024, nullptr, 1.f, 0, 0, 0);

    // scores = q@k^T * (1/32) + rel_bias, lower-triangular tiles only (batched)
    gemm_nt<1><<<dim3(16, 16, 4), 256>>>(q, k, att, 2048, 2048, 1024,
                                         rel_bias, 0.03125f,
                                         2048LL * 1024, 2048LL * 1024, 2048LL * 2048);

    // causal softmax, in place
    softmax_rows<<<8192, 256>>>(att);

    // att_out = P @ V (causal K bound)
    gemm_nn_causal<<<dim3(8, 16, 4), 256>>>(att, v, mix, 2048, 1024, 2048);

    // mix += grouped_conv(v) + conv_b
    conv_mix_kernel<<<dim3(8, 16, 4), 256>>>(v, wt, conv_b, mix);

    // gate logits = mix @ resg_w^T
    gemm_nt<0><<<dim3(8, 64, 1), 256>>>(mix, resg_w, gl, 8192, 1024, 1024, nullptr, 1.f, 0, 0, 0);

    // residual gate + layernorm
    fuse_res_ln<<<8192, 256>>>(x, gl, mix, resg_b, ln_g, ln_b, ln);

    // h = gelu(ln @ fc1_w^T + fc1_b)
    gemm_nt<2><<<dim3(4, 64, 1), 256>>>(ln, fc1_w, h, 8192, 512, 1024, fc1_b, 1.f, 0, 0, 0);

    // out = sigmoid(h @ fc2_w^T + fc2_b)
    fc2_sigmoid<<<1024, 256>>>(h, fc2_w, fc2_b, out);
}

// round 5
// speedup vs baseline: 1.3620x; 1.3620x over previous
#include <cuda_runtime.h>
#include <math.h>

// ---------------------------------------------------------------------------
// B=4, N=2048, D=1024, GROUPS=4.  All big GEMMs on tensor cores via
// 3xTF32 mma.sync.m16n8k8 (hi/lo split for ~fp32 accuracy).
// ---------------------------------------------------------------------------
#define BM 128
#define BN 128
#define BKK 16
#define P2    264        // floats per kk-row (132 float2)
#define KSOFF 1072       // 4*P2 + 16 pad between ks blocks
#define TILE_F 2144      // 2 * KSOFF floats per tile

// ------------------------------- scratch -----------------------------------
__device__ float g_xh[8388608], g_xl[8388608];
__device__ float g_qh[8388608], g_ql[8388608];
__device__ float g_kh[8388608], g_kl[8388608];
__device__ float g_vh[8388608], g_vl[8388608];
__device__ float g_att[16777216];                 // raw scores
__device__ float g_ph [16777216], g_pl[16777216]; // softmax probs hi/lo
__device__ float g_mix[8388608];                  // att_out (fp32)
__device__ float g_mh [8388608], g_ml[8388608];   // mix = att_out+conv, hi/lo
__device__ float g_gl [8388608];                  // gate logits
__device__ float g_lnh[8388608], g_lnl[8388608];
__device__ float g_h  [4194304];
__device__ float g_wqh[1048576], g_wql[1048576];
__device__ float g_wkh[1048576], g_wkl[1048576];
__device__ float g_wvh[1048576], g_wvl[1048576];
__device__ float g_rgh[1048576], g_rgl[1048576];
__device__ float g_f1h[524288],  g_f1l[524288];
__device__ float g_wth[786432],  g_wtl[786432];   // conv w: [co][tap*256+ci]

// ------------------------------- helpers -----------------------------------
__device__ __forceinline__ void tf32split(float x, float& hi, float& lo) {
    unsigned uh; asm("cvt.rna.tf32.f32 %0, %1;" : "=r"(uh) : "f"(x));
    hi = __uint_as_float(uh);
    unsigned ul; asm("cvt.rna.tf32.f32 %0, %1;" : "=r"(ul) : "f"(x - hi));
    lo = __uint_as_float(ul);
}

__device__ __forceinline__ void mma8(float* d, const unsigned* a, const unsigned* b) {
    asm("mma.sync.aligned.m16n8k8.row.col.f32.tf32.tf32.f32 "
        "{%0,%1,%2,%3}, {%4,%5,%6,%7}, {%8,%9}, {%0,%1,%2,%3};"
        : "+f"(d[0]), "+f"(d[1]), "+f"(d[2]), "+f"(d[3])
        : "r"(a[0]), "r"(a[1]), "r"(a[2]), "r"(a[3]), "r"(b[0]), "r"(b[1]));
}

// store one float4 along k (c = 0,4,8,12) for dimension index r
__device__ __forceinline__ void stash4(float* t, int r, int c, float4 v) {
    int ks  = c >> 3;
    int sel = (c >> 2) & 1;
    float* p = t + ks * KSOFF + r * 2 + sel;
    p[0]      = v.x;
    p[P2]     = v.y;
    p[2 * P2] = v.z;
    p[3 * P2] = v.w;
}
// NN variant: element rows along k, 4 consecutive n
__device__ __forceinline__ void stashNN(float* t, int k, int n, float4 v) {
    int ks  = k >> 3;
    int kk  = k & 3;
    int sel = (k >> 2) & 1;
    float* p = t + ks * KSOFF + kk * P2 + n * 2 + sel;
    p[0] = v.x; p[2] = v.y; p[4] = v.z; p[6] = v.w;
}
__device__ __forceinline__ void ldAfrag(const float* t, int ks, int mrow,
                                        int q4, int g, unsigned* a) {
    const float* base = t + ks * KSOFF + q4 * P2 + (mrow + g) * 2;
    float2 f0 = *(const float2*)base;
    float2 f1 = *(const float2*)(base + 16);
    a[0] = __float_as_uint(f0.x); a[2] = __float_as_uint(f0.y);
    a[1] = __float_as_uint(f1.x); a[3] = __float_as_uint(f1.y);
}
__device__ __forceinline__ void ldBfrag(const float* t, int ks, int ncol,
                                        int q4, int g, unsigned* b) {
    float2 f = *(const float2*)(t + ks * KSOFF + q4 * P2 + (ncol + g) * 2);
    b[0] = __float_as_uint(f.x); b[1] = __float_as_uint(f.y);
}

#define MMA_CORE(sAh, sAl, sBh, sBl, acc)                                    \
    _Pragma("unroll")                                                        \
    for (int ks = 0; ks < 2; ks++) {                                         \
        unsigned ah[4][4], al[4][4];                                         \
        _Pragma("unroll")                                                    \
        for (int t = 0; t < 4; t++) {                                        \
            ldAfrag(sAh, ks, wm * 64 + t * 16, q4, g, ah[t]);                \
            ldAfrag(sAl, ks, wm * 64 + t * 16, q4, g, al[t]);                \
        }                                                                    \
        _Pragma("unroll")                                                    \
        for (int u = 0; u < 4; u++) {                                        \
            unsigned bh[2], bl[2];                                           \
            ldBfrag(sBh, ks, wn * 32 + u * 8, q4, g, bh);                    \
            ldBfrag(sBl, ks, wn * 32 + u * 8, q4, g, bl);                    \
            _Pragma("unroll")                                                \
            for (int t = 0; t < 4; t++) {                                    \
                mma8(acc[t][u], ah[t], bh);                                  \
                mma8(acc[t][u], ah[t], bl);                                  \
                mma8(acc[t][u], al[t], bh);                                  \
            }                                                                \
        }                                                                    \
    }

// ---------------------------------------------------------------------------
// NT GEMM (A:[M,K], B:[N,K] row-major), hi/lo operands.
// MODE 0: plain fp32 C                    (res-gate)
// MODE 1: scores: C = acc*scale + rb2d[m*2048+n]; skip n0>m0; batched
// MODE 2: fc1: C = gelu_exact(acc + bias[n])
// MODE 3: split: C=hi(acc), C2=lo(acc)    (q/k/v)
// ---------------------------------------------------------------------------
template<int MODE>
__global__ void __launch_bounds__(256, 2)
gemm_tf32_nt(const float* __restrict__ Ah, const float* __restrict__ Al,
             const float* __restrict__ Bh, const float* __restrict__ Bl,
             float* __restrict__ C, float* __restrict__ C2,
             int M, int N, int K,
             const float* __restrict__ bias, float scale,
             long long sA, long long sB, long long sC) {
    int m0 = blockIdx.y * BM;
    int n0 = blockIdx.x * BN;
    if (MODE == 1 && n0 > m0) return;
    Ah += (long long)blockIdx.z * sA;  Al += (long long)blockIdx.z * sA;
    Bh += (long long)blockIdx.z * sB;  Bl += (long long)blockIdx.z * sB;
    C  += (long long)blockIdx.z * sC;

    __shared__ float sAh[TILE_F], sAl[TILE_F], sBh[TILE_F], sBl[TILE_F];

    int tid = threadIdx.x;
    int warp = tid >> 5, lane = tid & 31;
    int wm = warp >> 2, wn = warp & 3;
    int g = lane >> 2, q4 = lane & 3;

    float acc[4][4][4];
    #pragma unroll
    for (int t = 0; t < 4; t++)
        #pragma unroll
        for (int u = 0; u < 4; u++)
            #pragma unroll
            for (int j = 0; j < 4; j++) acc[t][u][j] = 0.f;

    for (int k0 = 0; k0 < K; k0 += BKK) {
        #pragma unroll
        for (int h = 0; h < 2; h++) {
            int idx = tid + h * 256;
            int r = idx >> 2;
            int c = (idx & 3) * 4;
            long long ao = (long long)(m0 + r) * K + k0 + c;
            stash4(sAh, r, c, *(const float4*)(Ah + ao));
            stash4(sAl, r, c, *(const float4*)(Al + ao));
            long long bo = (long long)(n0 + r) * K + k0 + c;
            stash4(sBh, r, c, *(const float4*)(Bh + bo));
            stash4(sBl, r, c, *(const float4*)(Bl + bo));
        }
        __syncthreads();
        MMA_CORE(sAh, sAl, sBh, sBl, acc)
        __syncthreads();
    }

    #pragma unroll
    for (int t = 0; t < 4; t++) {
        #pragma unroll
        for (int u = 0; u < 4; u++) {
            int m = m0 + wm * 64 + t * 16 + g;
            int n = n0 + wn * 32 + u * 8 + q4 * 2;
            float* a = acc[t][u];
            #pragma unroll
            for (int half = 0; half < 2; half++) {
                int mm = m + half * 8;
                float v0 = a[half * 2], v1 = a[half * 2 + 1];
                long long co = (long long)mm * N + n;
                if (MODE == 0) {
                    *(float2*)(C + co) = make_float2(v0, v1);
                } else if (MODE == 1) {
                    const float* bp = bias + (long long)mm * 2048 + n;
                    *(float2*)(C + co) = make_float2(v0 * scale + bp[0],
                                                     v1 * scale + bp[1]);
                } else if (MODE == 2) {
                    float z0 = v0 + bias[n], z1 = v1 + bias[n + 1];
                    v0 = 0.5f * z0 * (1.f + erff(z0 * 0.70710678118654752f));
                    v1 = 0.5f * z1 * (1.f + erff(z1 * 0.70710678118654752f));
                    *(float2*)(C + co) = make_float2(v0, v1);
                } else {
                    float h0, l0, h1, l1;
                    tf32split(v0, h0, l0);
                    tf32split(v1, h1, l1);
                    *(float2*)(C  + co) = make_float2(h0, h1);
                    *(float2*)(C2 + co) = make_float2(l0, l1);
                }
            }
        }
    }
}

// ---------------------------------------------------------------------------
// PV: C = P @ V (NN, batched, causal K bound). A = P hi/lo, B = V hi/lo.
// ---------------------------------------------------------------------------
__global__ void __launch_bounds__(256, 2)
gemm_tf32_pv(const float* __restrict__ Ah, const float* __restrict__ Al,
             const float* __restrict__ Bh, const float* __restrict__ Bl,
             float* __restrict__ C) {
    const int N = 1024, K = 2048;
    int m0 = blockIdx.y * BM;
    int n0 = blockIdx.x * BN;
    Ah += (long long)blockIdx.z * 2048 * 2048;
    Al += (long long)blockIdx.z * 2048 * 2048;
    Bh += (long long)blockIdx.z * 2048 * 1024;
    Bl += (long long)blockIdx.z * 2048 * 1024;
    C  += (long long)blockIdx.z * 2048 * 1024;
    int Keff = m0 + BM;

    __shared__ float sAh[TILE_F], sAl[TILE_F], sBh[TILE_F], sBl[TILE_F];

    int tid = threadIdx.x;
    int warp = tid >> 5, lane = tid & 31;
    int wm = warp >> 2, wn = warp & 3;
    int g = lane >> 2, q4 = lane & 3;

    float acc[4][4][4];
    #pragma unroll
    for (int t = 0; t < 4; t++)
        #pragma unroll
        for (int u = 0; u < 4; u++)
            #pragma unroll
            for (int j = 0; j < 4; j++) acc[t][u][j] = 0.f;

    for (int k0 = 0; k0 < Keff; k0 += BKK) {
        #pragma unroll
        for (int h = 0; h < 2; h++) {
            int idx = tid + h * 256;
            int r = idx >> 2;
            int c = (idx & 3) * 4;
            long long ao = (long long)(m0 + r) * K + k0 + c;
            stash4(sAh, r, c, *(const float4*)(Ah + ao));
            stash4(sAl, r, c, *(const float4*)(Al + ao));
            int kk = idx >> 5;
            int cc = (idx & 31) * 4;
            long long bo = (long long)(k0 + kk) * N + n0 + cc;
            stashNN(sBh, kk, cc, *(const float4*)(Bh + bo));
            stashNN(sBl, kk, cc, *(const float4*)(Bl + bo));
        }
        __syncthreads();
        MMA_CORE(sAh, sAl, sBh, sBl, acc)
        __syncthreads();
    }

    #pragma unroll
    for (int t = 0; t < 4; t++)
        #pragma unroll
        for (int u = 0; u < 4; u++) {
            int m = m0 + wm * 64 + t * 16 + g;
            int n = n0 + wn * 32 + u * 8 + q4 * 2;
            float* a = acc[t][u];
            *(float2*)(C + (long long)m * N + n)       = make_float2(a[0], a[1]);
            *(float2*)(C + (long long)(m + 8) * N + n) = make_float2(a[2], a[3]);
        }
}

// ---------------------------------------------------------------------------
// Grouped conv as K=768 NT GEMM (virtual shifted A from V hi/lo).
// Epilogue: mix = att_out + acc + conv_b, split into mh/ml.
// ---------------------------------------------------------------------------
__global__ void __launch_bounds__(256, 2)
conv_tf32(const float* __restrict__ Vh, const float* __restrict__ Vl,
          const float* __restrict__ Wh, const float* __restrict__ Wl,
          const float* __restrict__ cb, const float* __restrict__ mix,
          float* __restrict__ Mh, float* __restrict__ Ml) {
    int b  = blockIdx.z;
    int n0 = blockIdx.x * BN;    // c_out
    int m0 = blockIdx.y * BM;    // time
    int grp = n0 >> 8;
    const float* vhb = Vh + (long long)b * 2048 * 1024 + grp * 256;
    const float* vlb = Vl + (long long)b * 2048 * 1024 + grp * 256;

    __shared__ float sAh[TILE_F], sAl[TILE_F], sBh[TILE_F], sBl[TILE_F];

    int tid = threadIdx.x;
    int warp = tid >> 5, lane = tid & 31;
    int wm = warp >> 2, wn = warp & 3;
    int g = lane >> 2, q4 = lane & 3;

    float acc[4][4][4];
    #pragma unroll
    for (int t = 0; t < 4; t++)
        #pragma unroll
        for (int u = 0; u < 4; u++)
            #pragma unroll
            for (int j = 0; j < 4; j++) acc[t][u][j] = 0.f;

    for (int k0 = 0; k0 < 768; k0 += BKK) {
        #pragma unroll
        for (int h = 0; h < 2; h++) {
            int idx = tid + h * 256;
            int r = idx >> 2;
            int c = (idx & 3) * 4;
            int kg  = k0 + c;
            int tap = kg >> 8;
            int ci  = kg & 255;
            int row = m0 + r + tap - 1;
            float4 vh4 = make_float4(0.f, 0.f, 0.f, 0.f);
            float4 vl4 = vh4;
            if (row >= 0 && row < 2048) {
                vh4 = *(const float4*)(vhb + (long long)row * 1024 + ci);
                vl4 = *(const float4*)(vlb + (long long)row * 1024 + ci);
            }
            stash4(sAh, r, c, vh4);
            stash4(sAl, r, c, vl4);
            long long bo = (long long)(n0 + r) * 768 + k0 + c;
            stash4(sBh, r, c, *(const float4*)(Wh + bo));
            stash4(sBl, r, c, *(const float4*)(Wl + bo));
        }
        __syncthreads();
        MMA_CORE(sAh, sAl, sBh, sBl, acc)
        __syncthreads();
    }

    #pragma unroll
    for (int t = 0; t < 4; t++)
        #pragma unroll
        for (int u = 0; u < 4; u++) {
            int m = m0 + wm * 64 + t * 16 + g;
            int n = n0 + wn * 32 + u * 8 + q4 * 2;
            float* a = acc[t][u];
            #pragma unroll
            for (int half = 0; half < 2; half++) {
                int mm = m + half * 8;
                long long co = ((long long)b * 2048 + mm) * 1024 + n;
                float v0 = mix[co]     + a[half * 2]     + cb[n];
                float v1 = mix[co + 1] + a[half * 2 + 1] + cb[n + 1];
                float h0, l0, h1, l1;
                tf32split(v0, h0, l0);
                tf32split(v1, h1, l1);
                *(float2*)(Mh + co) = make_float2(h0, h1);
                *(float2*)(Ml + co) = make_float2(l0, l1);
            }
        }
}

// ------------------------- small / elementwise kernels ----------------------
__global__ void split_arr(const float* __restrict__ s, float* __restrict__ h,
                          float* __restrict__ l, int n4) {
    int i = blockIdx.x * blockDim.x + threadIdx.x;
    if (i < n4) {
        float4 v = ((const float4*)s)[i];
        float4 hv, lv;
        tf32split(v.x, hv.x, lv.x); tf32split(v.y, hv.y, lv.y);
        tf32split(v.z, hv.z, lv.z); tf32split(v.w, hv.w, lv.w);
        ((float4*)h)[i] = hv;
        ((float4*)l)[i] = lv;
    }
}

// conv_w [co][ci][tap] -> [co][tap*256+ci], split hi/lo
__global__ void transpose_w_kernel(const float* __restrict__ cw,
                                   float* __restrict__ wh, float* __restrict__ wl) {
    int i = blockIdx.x * blockDim.x + threadIdx.x;
    if (i < 262144) {
        int co = i >> 8, ci = i & 255;
        const float* src = cw + (long long)co * 768 + ci * 3;
        #pragma unroll
        for (int tap = 0; tap < 3; tap++) {
            float h, l;
            tf32split(src[tap], h, l);
            long long o = (long long)co * 768 + tap * 256 + ci;
            wh[o] = h; wl[o] = l;
        }
    }
}

// causal softmax: read raw scores, write prob hi/lo (zero-padded to Lpad)
__global__ void softmax_rows(const float* __restrict__ att,
                             float* __restrict__ ph, float* __restrict__ pl) {
    int row = blockIdx.x;
    int b = row >> 11;
    int i = row & 2047;
    int L = i + 1;
    int Lpad = ((i >> 7) + 1) << 7;
    const float* s = att + ((long long)b * 2048 + i) * 2048;
    float* oh = ph + ((long long)b * 2048 + i) * 2048;
    float* ol = pl + ((long long)b * 2048 + i) * 2048;
    int tid = threadIdx.x;

    float v[8];
    float m = -3.0e38f;
    #pragma unroll
    for (int r = 0; r < 8; r++) {
        int j = r * 256 + tid;
        v[r] = (j < L) ? s[j] : -3.0e38f;
        m = fmaxf(m, v[r]);
    }
    __shared__ float red[256];
    red[tid] = m; __syncthreads();
    #pragma unroll
    for (int o = 128; o > 0; o >>= 1) {
        if (tid < o) red[tid] = fmaxf(red[tid], red[tid + o]);
        __syncthreads();
    }
    m = red[0]; __syncthreads();

    float sum = 0.f;
    #pragma unroll
    for (int r = 0; r < 8; r++) { v[r] = __expf(v[r] - m); sum += v[r]; }
    red[tid] = sum; __syncthreads();
    #pragma unroll
    for (int o = 128; o > 0; o >>= 1) {
        if (tid < o) red[tid] += red[tid + o];
        __syncthreads();
    }
    float inv = 1.0f / red[0];
    #pragma unroll
    for (int r = 0; r < 8; r++) {
        int j = r * 256 + tid;
        if (j < Lpad) {
            float p = (j < L) ? v[r] * inv : 0.f;
            float h, l;
            tf32split(p, h, l);
            oh[j] = h; ol[j] = l;
        }
    }
}

// t = x + sigmoid(gl + rb) * (mh+ml); LayerNorm(t) -> lnh/lnl (split)
__global__ void fuse_res_ln(const float* __restrict__ x,
                            const float* __restrict__ gl,
                            const float* __restrict__ mh,
                            const float* __restrict__ ml,
                            const float* __restrict__ rb,
                            const float* __restrict__ lg,
                            const float* __restrict__ lb,
                            float* __restrict__ lnh, float* __restrict__ lnl) {
    int row = blockIdx.x;
    int tid = threadIdx.x;
    int c = tid * 4;
    long long base = (long long)row * 1024 + c;
    float4 xv = *(const float4*)(x + base);
    float4 gv = *(const float4*)(gl + base);
    float4 mhv = *(const float4*)(mh + base);
    float4 mlv = *(const float4*)(ml + base);
    float4 bv = *(const float4*)(rb + c);
    float m0 = mhv.x + mlv.x, m1 = mhv.y + mlv.y;
    float m2 = mhv.z + mlv.z, m3 = mhv.w + mlv.w;
    float t0 = xv.x + m0 / (1.f + __expf(-(gv.x + bv.x)));
    float t1 = xv.y + m1 / (1.f + __expf(-(gv.y + bv.y)));
    float t2 = xv.z + m2 / (1.f + __expf(-(gv.z + bv.z)));
    float t3 = xv.w + m3 / (1.f + __expf(-(gv.w + bv.w)));

    float s  = t0 + t1 + t2 + t3;
    float ss = t0 * t0 + t1 * t1 + t2 * t2 + t3 * t3;
    __shared__ float r1[256], r2[256];
    r1[tid] = s; r2[tid] = ss; __syncthreads();
    #pragma unroll
    for (int o = 128; o > 0; o >>= 1) {
        if (tid < o) { r1[tid] += r1[tid + o]; r2[tid] += r2[tid + o]; }
        __syncthreads();
    }
    float mu  = r1[0] * (1.0f / 1024.0f);
    float var = r2[0] * (1.0f / 1024.0f) - mu * mu;
    float inv = rsqrtf(var + 1e-5f);
    float4 gw = *(const float4*)(lg + c);
    float4 bw = *(const float4*)(lb + c);
    float o0 = (t0 - mu) * inv * gw.x + bw.x;
    float o1 = (t1 - mu) * inv * gw.y + bw.y;
    float o2 = (t2 - mu) * inv * gw.z + bw.z;
    float o3 = (t3 - mu) * inv * gw.w + bw.w;
    float4 hv, lv;
    tf32split(o0, hv.x, lv.x); tf32split(o1, hv.y, lv.y);
    tf32split(o2, hv.z, lv.z); tf32split(o3, hv.w, lv.w);
    *(float4*)(lnh + base) = hv;
    *(float4*)(lnl + base) = lv;
}

__global__ void fc2_sigmoid(const float* __restrict__ h,
                            const float* __restrict__ w,
                            const float* __restrict__ b,
                            float* __restrict__ out) {
    int warp = (blockIdx.x * blockDim.x + threadIdx.x) >> 5;
    int lane = threadIdx.x & 31;
    const float* hr = h + (long long)warp * 512;
    float s = 0.f;
    #pragma unroll
    for (int j = 0; j < 512; j += 32) s += hr[j + lane] * w[j + lane];
    #pragma unroll
    for (int o = 16; o > 0; o >>= 1) s += __shfl_down_sync(0xffffffffu, s, o);
    if (lane == 0) out[warp] = 1.0f / (1.0f + __expf(-(s + b[0])));
}

// ---------------------------------------------------------------------------
extern "C" void kernel_launch(void* const* d_in, const int* in_sizes, int n_in,
                              void* d_out, int out_size) {
    const float* x        = (const float*)d_in[0];
    const float* Wq       = (const float*)d_in[1];
    const float* Wk       = (const float*)d_in[2];
    const float* Wv       = (const float*)d_in[3];
    const float* rel_bias = (const float*)d_in[4];
    const float* conv_w   = (const float*)d_in[5];
    const float* conv_b   = (const float*)d_in[6];
    const float* resg_w   = (const float*)d_in[7];
    const float* resg_b   = (const float*)d_in[8];
    const float* ln_g     = (const float*)d_in[9];
    const float* ln_b     = (const float*)d_in[10];
    const float* fc1_w    = (const float*)d_in[11];
    const float* fc1_b    = (const float*)d_in[12];
    const float* fc2_w    = (const float*)d_in[13];
    const float* fc2_b    = (const float*)d_in[14];
    float* out = (float*)d_out;

    float *xh,*xl,*qh,*ql,*kh,*kl,*vh,*vl,*att,*ph,*pl,*mix,*mh,*ml,*gl;
    float *lnh,*lnl,*hbuf,*wqh,*wql,*wkh,*wkl,*wvh,*wvl,*rgh,*rgl,*f1h,*f1l,*wth,*wtl;
    cudaGetSymbolAddress((void**)&xh,  g_xh);  cudaGetSymbolAddress((void**)&xl,  g_xl);
    cudaGetSymbolAddress((void**)&qh,  g_qh);  cudaGetSymbolAddress((void**)&ql,  g_ql);
    cudaGetSymbolAddress((void**)&kh,  g_kh);  cudaGetSymbolAddress((void**)&kl,  g_kl);
    cudaGetSymbolAddress((void**)&vh,  g_vh);  cudaGetSymbolAddress((void**)&vl,  g_vl);
    cudaGetSymbolAddress((void**)&att, g_att);
    cudaGetSymbolAddress((void**)&ph,  g_ph);  cudaGetSymbolAddress((void**)&pl,  g_pl);
    cudaGetSymbolAddress((void**)&mix, g_mix);
    cudaGetSymbolAddress((void**)&mh,  g_mh);  cudaGetSymbolAddress((void**)&ml,  g_ml);
    cudaGetSymbolAddress((void**)&gl,  g_gl);
    cudaGetSymbolAddress((void**)&lnh, g_lnh); cudaGetSymbolAddress((void**)&lnl, g_lnl);
    cudaGetSymbolAddress((void**)&hbuf,g_h);
    cudaGetSymbolAddress((void**)&wqh, g_wqh); cudaGetSymbolAddress((void**)&wql, g_wql);
    cudaGetSymbolAddress((void**)&wkh, g_wkh); cudaGetSymbolAddress((void**)&wkl, g_wkl);
    cudaGetSymbolAddress((void**)&wvh, g_wvh); cudaGetSymbolAddress((void**)&wvl, g_wvl);
    cudaGetSymbolAddress((void**)&rgh, g_rgh); cudaGetSymbolAddress((void**)&rgl, g_rgl);
    cudaGetSymbolAddress((void**)&f1h, g_f1h); cudaGetSymbolAddress((void**)&f1l, g_f1l);
    cudaGetSymbolAddress((void**)&wth, g_wth); cudaGetSymbolAddress((void**)&wtl, g_wtl);

    // operand splits
    split_arr<<<8192, 256>>>(x, xh, xl, 2097152);
    split_arr<<<1024, 256>>>(Wq, wqh, wql, 262144);
    split_arr<<<1024, 256>>>(Wk, wkh, wkl, 262144);
    split_arr<<<1024, 256>>>(Wv, wvh, wvl, 262144);
    split_arr<<<1024, 256>>>(resg_w, rgh, rgl, 262144);
    split_arr<<<512, 256>>>(fc1_w, f1h, f1l, 131072);
    transpose_w_kernel<<<1024, 256>>>(conv_w, wth, wtl);

    // q/k/v projections (split outputs)
    gemm_tf32_nt<3><<<dim3(8, 64, 1), 256>>>(xh, xl, wqh, wql, qh, ql,
                                             8192, 1024, 1024, nullptr, 1.f, 0, 0, 0);
    gemm_tf32_nt<3><<<dim3(8, 64, 1), 256>>>(xh, xl, wkh, wkl, kh, kl,
                                             8192, 1024, 1024, nullptr, 1.f, 0, 0, 0);
    gemm_tf32_nt<3><<<dim3(8, 64, 1), 256>>>(xh, xl, wvh, wvl, vh, vl,
                                             8192, 1024, 1024, nullptr, 1.f, 0, 0, 0);

    // scores (lower-tri tiles only, batched) -> raw fp32
    gemm_tf32_nt<1><<<dim3(16, 16, 4), 256>>>(qh, ql, kh, kl, att, nullptr,
                                              2048, 2048, 1024, rel_bias, 0.03125f,
                                              2048LL * 1024, 2048LL * 1024,
                                              2048LL * 2048);

    // softmax -> prob hi/lo
    softmax_rows<<<8192, 256>>>(att, ph, pl);

    // att_out = P @ V
    gemm_tf32_pv<<<dim3(8, 16, 4), 256>>>(ph, pl, vh, vl, mix);

    // mix = att_out + conv(v) + conv_b  -> hi/lo
    conv_tf32<<<dim3(8, 16, 4), 256>>>(vh, vl, wth, wtl, conv_b, mix, mh, ml);

    // gate logits
    gemm_tf32_nt<0><<<dim3(8, 64, 1), 256>>>(mh, ml, rgh, rgl, gl, nullptr,
                                             8192, 1024, 1024, nullptr, 1.f, 0, 0, 0);

    // residual gate + layernorm -> hi/lo
    fuse_res_ln<<<8192, 256>>>(x, gl, mh, ml, resg_b, ln_g, ln_b, lnh, lnl);

    // fc1 + gelu
    gemm_tf32_nt<2><<<dim3(4, 64, 1), 256>>>(lnh, lnl, f1h, f1l, hbuf, nullptr,
                                             8192, 512, 1024, fc1_b, 1.f, 0, 0, 0);

    // fc2 + sigmoid
    fc2_sigmoid<<<1024, 256>>>(hbuf, fc2_w, fc2_b, out);
}

// round 7
// speedup vs baseline: 1.3632x; 1.0009x over previous
#include <cuda_runtime.h>
#include <math.h>

// ---------------------------------------------------------------------------
// B=4, N=2048, D=1024, GROUPS=4.  All big GEMMs on tensor cores via
// 3xTF32 mma.sync.m16n8k8 (hi/lo split for ~fp32 accuracy).
// ---------------------------------------------------------------------------
#define BM 128
#define BN 128
#define BKK 16
#define P2    264        // floats per kk-row (132 float2)
#define KSOFF 1072       // 4*P2 + 16 pad between ks blocks
#define TILE_F 2144      // 2 * KSOFF floats per tile

// ------------------------------- scratch -----------------------------------
__device__ float g_xh[8388608], g_xl[8388608];
__device__ float g_qh[8388608], g_ql[8388608];
__device__ float g_kh[8388608], g_kl[8388608];
__device__ float g_vh[8388608], g_vl[8388608];
__device__ float g_att[16777216];                 // raw scores
__device__ float g_ph [16777216], g_pl[16777216]; // softmax probs hi/lo
__device__ float g_mix[8388608];                  // att_out (fp32)
__device__ float g_mh [8388608], g_ml[8388608];   // mix = att_out+conv, hi/lo
__device__ float g_gl [8388608];                  // gate logits
__device__ float g_lnh[8388608], g_lnl[8388608];
__device__ float g_h  [4194304];
__device__ float g_wqh[1048576], g_wql[1048576];
__device__ float g_wkh[1048576], g_wkl[1048576];
__device__ float g_wvh[1048576], g_wvl[1048576];
__device__ float g_rgh[1048576], g_rgl[1048576];
__device__ float g_f1h[524288],  g_f1l[524288];
__device__ float g_wth[786432],  g_wtl[786432];   // conv w: [co][tap*256+ci]

// ------------------------------- helpers -----------------------------------
__device__ __forceinline__ void tf32split(float x, float& hi, float& lo) {
    unsigned uh; asm("cvt.rna.tf32.f32 %0, %1;" : "=r"(uh) : "f"(x));
    hi = __uint_as_float(uh);
    unsigned ul; asm("cvt.rna.tf32.f32 %0, %1;" : "=r"(ul) : "f"(x - hi));
    lo = __uint_as_float(ul);
}

__device__ __forceinline__ void mma8(float* d, const unsigned* a, const unsigned* b) {
    asm("mma.sync.aligned.m16n8k8.row.col.f32.tf32.tf32.f32 "
        "{%0,%1,%2,%3}, {%4,%5,%6,%7}, {%8,%9}, {%0,%1,%2,%3};"
        : "+f"(d[0]), "+f"(d[1]), "+f"(d[2]), "+f"(d[3])
        : "r"(a[0]), "r"(a[1]), "r"(a[2]), "r"(a[3]), "r"(b[0]), "r"(b[1]));
}

// store one float4 along k (c = 0,4,8,12) for dimension index r
__device__ __forceinline__ void stash4(float* t, int r, int c, float4 v) {
    int ks  = c >> 3;
    int sel = (c >> 2) & 1;
    float* p = t + ks * KSOFF + r * 2 + sel;
    p[0]      = v.x;
    p[P2]     = v.y;
    p[2 * P2] = v.z;
    p[3 * P2] = v.w;
}
// NN variant: element rows along k, 4 consecutive n
__device__ __forceinline__ void stashNN(float* t, int k, int n, float4 v) {
    int ks  = k >> 3;
    int kk  = k & 3;
    int sel = (k >> 2) & 1;
    float* p = t + ks * KSOFF + kk * P2 + n * 2 + sel;
    p[0] = v.x; p[2] = v.y; p[4] = v.z; p[6] = v.w;
}
__device__ __forceinline__ void ldAfrag(const float* t, int ks, int mrow,
                                        int q4, int g, unsigned* a) {
    const float* base = t + ks * KSOFF + q4 * P2 + (mrow + g) * 2;
    float2 f0 = *(const float2*)base;
    float2 f1 = *(const float2*)(base + 16);
    a[0] = __float_as_uint(f0.x); a[2] = __float_as_uint(f0.y);
    a[1] = __float_as_uint(f1.x); a[3] = __float_as_uint(f1.y);
}
__device__ __forceinline__ void ldBfrag(const float* t, int ks, int ncol,
                                        int q4, int g, unsigned* b) {
    float2 f = *(const float2*)(t + ks * KSOFF + q4 * P2 + (ncol + g) * 2);
    b[0] = __float_as_uint(f.x); b[1] = __float_as_uint(f.y);
}

#define MMA_CORE(sAh, sAl, sBh, sBl, acc)                                    \
    _Pragma("unroll")                                                        \
    for (int ks = 0; ks < 2; ks++) {                                         \
        unsigned ah[4][4], al[4][4];                                         \
        _Pragma("unroll")                                                    \
        for (int t = 0; t < 4; t++) {                                        \
            ldAfrag(sAh, ks, wm * 64 + t * 16, q4, g, ah[t]);                \
            ldAfrag(sAl, ks, wm * 64 + t * 16, q4, g, al[t]);                \
        }                                                                    \
        _Pragma("unroll")                                                    \
        for (int u = 0; u < 4; u++) {                                        \
            unsigned bh[2], bl[2];                                           \
            ldBfrag(sBh, ks, wn * 32 + u * 8, q4, g, bh);                    \
            ldBfrag(sBl, ks, wn * 32 + u * 8, q4, g, bl);                    \
            _Pragma("unroll")                                                \
            for (int t = 0; t < 4; t++) {                                    \
                mma8(acc[t][u], ah[t], bh);                                  \
                mma8(acc[t][u], ah[t], bl);                                  \
                mma8(acc[t][u], al[t], bh);                                  \
            }                                                                \
        }                                                                    \
    }

// ---------------------------------------------------------------------------
// NT GEMM (A:[M,K], B:[N,K] row-major), hi/lo operands.
// MODE 0: plain fp32 C                    (res-gate)
// MODE 1: scores: C = acc*scale + rb2d[m*2048+n]; skip n0>m0; batched
// MODE 2: fc1: C = gelu_exact(acc + bias[n])
// MODE 3: split: C=hi(acc), C2=lo(acc)    (q/k/v)
// ---------------------------------------------------------------------------
template<int MODE>
__global__ void __launch_bounds__(256, 2)
gemm_tf32_nt(const float* __restrict__ Ah, const float* __restrict__ Al,
             const float* __restrict__ Bh, const float* __restrict__ Bl,
             float* __restrict__ C, float* __restrict__ C2,
             int M, int N, int K,
             const float* __restrict__ bias, float scale,
             long long sA, long long sB, long long sC) {
    int m0 = blockIdx.y * BM;
    int n0 = blockIdx.x * BN;
    if (MODE == 1 && n0 > m0) return;
    Ah += (long long)blockIdx.z * sA;  Al += (long long)blockIdx.z * sA;
    Bh += (long long)blockIdx.z * sB;  Bl += (long long)blockIdx.z * sB;
    C  += (long long)blockIdx.z * sC;

    __shared__ float sAh[TILE_F], sAl[TILE_F], sBh[TILE_F], sBl[TILE_F];

    int tid = threadIdx.x;
    int warp = tid >> 5, lane = tid & 31;
    int wm = warp >> 2, wn = warp & 3;
    int g = lane >> 2, q4 = lane & 3;

    float acc[4][4][4];
    #pragma unroll
    for (int t = 0; t < 4; t++)
        #pragma unroll
        for (int u = 0; u < 4; u++)
            #pragma unroll
            for (int j = 0; j < 4; j++) acc[t][u][j] = 0.f;

    for (int k0 = 0; k0 < K; k0 += BKK) {
        #pragma unroll
        for (int h = 0; h < 2; h++) {
            int idx = tid + h * 256;
            int r = idx >> 2;
            int c = (idx & 3) * 4;
            long long ao = (long long)(m0 + r) * K + k0 + c;
            stash4(sAh, r, c, *(const float4*)(Ah + ao));
            stash4(sAl, r, c, *(const float4*)(Al + ao));
            long long bo = (long long)(n0 + r) * K + k0 + c;
            stash4(sBh, r, c, *(const float4*)(Bh + bo));
            stash4(sBl, r, c, *(const float4*)(Bl + bo));
        }
        __syncthreads();
        MMA_CORE(sAh, sAl, sBh, sBl, acc)
        __syncthreads();
    }

    #pragma unroll
    for (int t = 0; t < 4; t++) {
        #pragma unroll
        for (int u = 0; u < 4; u++) {
            int m = m0 + wm * 64 + t * 16 + g;
            int n = n0 + wn * 32 + u * 8 + q4 * 2;
            float* a = acc[t][u];
            #pragma unroll
            for (int half = 0; half < 2; half++) {
                int mm = m + half * 8;
                float v0 = a[half * 2], v1 = a[half * 2 + 1];
                long long co = (long long)mm * N + n;
                if (MODE == 0) {
                    *(float2*)(C + co) = make_float2(v0, v1);
                } else if (MODE == 1) {
                    const float* bp = bias + (long long)mm * 2048 + n;
                    *(float2*)(C + co) = make_float2(v0 * scale + bp[0],
                                                     v1 * scale + bp[1]);
                } else if (MODE == 2) {
                    float z0 = v0 + bias[n], z1 = v1 + bias[n + 1];
                    v0 = 0.5f * z0 * (1.f + erff(z0 * 0.70710678118654752f));
                    v1 = 0.5f * z1 * (1.f + erff(z1 * 0.70710678118654752f));
                    *(float2*)(C + co) = make_float2(v0, v1);
                } else {
                    float h0, l0, h1, l1;
                    tf32split(v0, h0, l0);
                    tf32split(v1, h1, l1);
                    *(float2*)(C  + co) = make_float2(h0, h1);
                    *(float2*)(C2 + co) = make_float2(l0, l1);
                }
            }
        }
    }
}

// ---------------------------------------------------------------------------
// PV: C = P @ V (NN, batched, causal K bound). A = P hi/lo, B = V hi/lo.
// ---------------------------------------------------------------------------
__global__ void __launch_bounds__(256, 2)
gemm_tf32_pv(const float* __restrict__ Ah, const float* __restrict__ Al,
             const float* __restrict__ Bh, const float* __restrict__ Bl,
             float* __restrict__ C) {
    const int N = 1024, K = 2048;
    int m0 = blockIdx.y * BM;
    int n0 = blockIdx.x * BN;
    Ah += (long long)blockIdx.z * 2048 * 2048;
    Al += (long long)blockIdx.z * 2048 * 2048;
    Bh += (long long)blockIdx.z * 2048 * 1024;
    Bl += (long long)blockIdx.z * 2048 * 1024;
    C  += (long long)blockIdx.z * 2048 * 1024;
    int Keff = m0 + BM;

    __shared__ float sAh[TILE_F], sAl[TILE_F], sBh[TILE_F], sBl[TILE_F];

    int tid = threadIdx.x;
    int warp = tid >> 5, lane = tid & 31;
    int wm = warp >> 2, wn = warp & 3;
    int g = lane >> 2, q4 = lane & 3;

    float acc[4][4][4];
    #pragma unroll
    for (int t = 0; t < 4; t++)
        #pragma unroll
        for (int u = 0; u < 4; u++)
            #pragma unroll
            for (int j = 0; j < 4; j++) acc[t][u][j] = 0.f;

    for (int k0 = 0; k0 < Keff; k0 += BKK) {
        #pragma unroll
        for (int h = 0; h < 2; h++) {
            int idx = tid + h * 256;
            int r = idx >> 2;
            int c = (idx & 3) * 4;
            long long ao = (long long)(m0 + r) * K + k0 + c;
            stash4(sAh, r, c, *(const float4*)(Ah + ao));
            stash4(sAl, r, c, *(const float4*)(Al + ao));
            int kk = idx >> 5;
            int cc = (idx & 31) * 4;
            long long bo = (long long)(k0 + kk) * N + n0 + cc;
            stashNN(sBh, kk, cc, *(const float4*)(Bh + bo));
            stashNN(sBl, kk, cc, *(const float4*)(Bl + bo));
        }
        __syncthreads();
        MMA_CORE(sAh, sAl, sBh, sBl, acc)
        __syncthreads();
    }

    #pragma unroll
    for (int t = 0; t < 4; t++)
        #pragma unroll
        for (int u = 0; u < 4; u++) {
            int m = m0 + wm * 64 + t * 16 + g;
            int n = n0 + wn * 32 + u * 8 + q4 * 2;
            float* a = acc[t][u];
            *(float2*)(C + (long long)m * N + n)       = make_float2(a[0], a[1]);
            *(float2*)(C + (long long)(m + 8) * N + n) = make_float2(a[2], a[3]);
        }
}

// ---------------------------------------------------------------------------
// Grouped conv as K=768 NT GEMM (virtual shifted A from V hi/lo).
// Epilogue: mix = att_out + acc + conv_b, split into mh/ml.
// ---------------------------------------------------------------------------
__global__ void __launch_bounds__(256, 2)
conv_tf32(const float* __restrict__ Vh, const float* __restrict__ Vl,
          const float* __restrict__ Wh, const float* __restrict__ Wl,
          const float* __restrict__ cb, const float* __restrict__ mix,
          float* __restrict__ Mh, float* __restrict__ Ml) {
    int b  = blockIdx.z;
    int n0 = blockIdx.x * BN;    // c_out
    int m0 = blockIdx.y * BM;    // time
    int grp = n0 >> 8;
    const float* vhb = Vh + (long long)b * 2048 * 1024 + grp * 256;
    const float* vlb = Vl + (long long)b * 2048 * 1024 + grp * 256;

    __shared__ float sAh[TILE_F], sAl[TILE_F], sBh[TILE_F], sBl[TILE_F];

    int tid = threadIdx.x;
    int warp = tid >> 5, lane = tid & 31;
    int wm = warp >> 2, wn = warp & 3;
    int g = lane >> 2, q4 = lane & 3;

    float acc[4][4][4];
    #pragma unroll
    for (int t = 0; t < 4; t++)
        #pragma unroll
        for (int u = 0; u < 4; u++)
            #pragma unroll
            for (int j = 0; j < 4; j++) acc[t][u][j] = 0.f;

    for (int k0 = 0; k0 < 768; k0 += BKK) {
        #pragma unroll
        for (int h = 0; h < 2; h++) {
            int idx = tid + h * 256;
            int r = idx >> 2;
            int c = (idx & 3) * 4;
            int kg  = k0 + c;
            int tap = kg >> 8;
            int ci  = kg & 255;
            int row = m0 + r + tap - 1;
            float4 vh4 = make_float4(0.f, 0.f, 0.f, 0.f);
            float4 vl4 = vh4;
            if (row >= 0 && row < 2048) {
                vh4 = *(const float4*)(vhb + (long long)row * 1024 + ci);
                vl4 = *(const float4*)(vlb + (long long)row * 1024 + ci);
            }
            stash4(sAh, r, c, vh4);
            stash4(sAl, r, c, vl4);
            long long bo = (long long)(n0 + r) * 768 + k0 + c;
            stash4(sBh, r, c, *(const float4*)(Wh + bo));
            stash4(sBl, r, c, *(const float4*)(Wl + bo));
        }
        __syncthreads();
        MMA_CORE(sAh, sAl, sBh, sBl, acc)
        __syncthreads();
    }

    #pragma unroll
    for (int t = 0; t < 4; t++)
        #pragma unroll
        for (int u = 0; u < 4; u++) {
            int m = m0 + wm * 64 + t * 16 + g;
            int n = n0 + wn * 32 + u * 8 + q4 * 2;
            float* a = acc[t][u];
            #pragma unroll
            for (int half = 0; half < 2; half++) {
                int mm = m + half * 8;
                long long co = ((long long)b * 2048 + mm) * 1024 + n;
                float v0 = mix[co]     + a[half * 2]     + cb[n];
                float v1 = mix[co + 1] + a[half * 2 + 1] + cb[n + 1];
                float h0, l0, h1, l1;
                tf32split(v0, h0, l0);
                tf32split(v1, h1, l1);
                *(float2*)(Mh + co) = make_float2(h0, h1);
                *(float2*)(Ml + co) = make_float2(l0, l1);
            }
        }
}

// ------------------------- small / elementwise kernels ----------------------
__global__ void split_arr(const float* __restrict__ s, float* __restrict__ h,
                          float* __restrict__ l, int n4) {
    int i = blockIdx.x * blockDim.x + threadIdx.x;
    if (i < n4) {
        float4 v = ((const float4*)s)[i];
        float4 hv, lv;
        tf32split(v.x, hv.x, lv.x); tf32split(v.y, hv.y, lv.y);
        tf32split(v.z, hv.z, lv.z); tf32split(v.w, hv.w, lv.w);
        ((float4*)h)[i] = hv;
        ((float4*)l)[i] = lv;
    }
}

// conv_w [co][ci][tap] -> [co][tap*256+ci], split hi/lo
__global__ void transpose_w_kernel(const float* __restrict__ cw,
                                   float* __restrict__ wh, float* __restrict__ wl) {
    int i = blockIdx.x * blockDim.x + threadIdx.x;
    if (i < 262144) {
        int co = i >> 8, ci = i & 255;
        const float* src = cw + (long long)co * 768 + ci * 3;
        #pragma unroll
        for (int tap = 0; tap < 3; tap++) {
            float h, l;
            tf32split(src[tap], h, l);
            long long o = (long long)co * 768 + tap * 256 + ci;
            wh[o] = h; wl[o] = l;
        }
    }
}

// causal softmax: read raw scores, write prob hi/lo (zero-padded to Lpad)
__global__ void softmax_rows(const float* __restrict__ att,
                             float* __restrict__ ph, float* __restrict__ pl) {
    int row = blockIdx.x;
    int b = row >> 11;
    int i = row & 2047;
    int L = i + 1;
    int Lpad = ((i >> 7) + 1) << 7;
    const float* s = att + ((long long)b * 2048 + i) * 2048;
    float* oh = ph + ((long long)b * 2048 + i) * 2048;
    float* ol = pl + ((long long)b * 2048 + i) * 2048;
    int tid = threadIdx.x;

    float v[8];
    float m = -3.0e38f;
    #pragma unroll
    for (int r = 0; r < 8; r++) {
        int j = r * 256 + tid;
        v[r] = (j < L) ? s[j] : -3.0e38f;
        m = fmaxf(m, v[r]);
    }
    __shared__ float red[256];
    red[tid] = m; __syncthreads();
    #pragma unroll
    for (int o = 128; o > 0; o >>= 1) {
        if (tid < o) red[tid] = fmaxf(red[tid], red[tid + o]);
        __syncthreads();
    }
    m = red[0]; __syncthreads();

    float sum = 0.f;
    #pragma unroll
    for (int r = 0; r < 8; r++) { v[r] = __expf(v[r] - m); sum += v[r]; }
    red[tid] = sum; __syncthreads();
    #pragma unroll
    for (int o = 128; o > 0; o >>= 1) {
        if (tid < o) red[tid] += red[tid + o];
        __syncthreads();
    }
    float inv = 1.0f / red[0];
    #pragma unroll
    for (int r = 0; r < 8; r++) {
        int j = r * 256 + tid;
        if (j < Lpad) {
            float p = (j < L) ? v[r] * inv : 0.f;
            float h, l;
            tf32split(p, h, l);
            oh[j] = h; ol[j] = l;
        }
    }
}

// t = x + sigmoid(gl + rb) * (mh+ml); LayerNorm(t) -> lnh/lnl (split)
__global__ void fuse_res_ln(const float* __restrict__ x,
                            const float* __restrict__ gl,
                            const float* __restrict__ mh,
                            const float* __restrict__ ml,
                            const float* __restrict__ rb,
                            const float* __restrict__ lg,
                            const float* __restrict__ lb,
                            float* __restrict__ lnh, float* __restrict__ lnl) {
    int row = blockIdx.x;
    int tid = threadIdx.x;
    int c = tid * 4;
    long long base = (long long)row * 1024 + c;
    float4 xv = *(const float4*)(x + base);
    float4 gv = *(const float4*)(gl + base);
    float4 mhv = *(const float4*)(mh + base);
    float4 mlv = *(const float4*)(ml + base);
    float4 bv = *(const float4*)(rb + c);
    float m0 = mhv.x + mlv.x, m1 = mhv.y + mlv.y;
    float m2 = mhv.z + mlv.z, m3 = mhv.w + mlv.w;
    float t0 = xv.x + m0 / (1.f + __expf(-(gv.x + bv.x)));
    float t1 = xv.y + m1 / (1.f + __expf(-(gv.y + bv.y)));
    float t2 = xv.z + m2 / (1.f + __expf(-(gv.z + bv.z)));
    float t3 = xv.w + m3 / (1.f + __expf(-(gv.w + bv.w)));

    float s  = t0 + t1 + t2 + t3;
    float ss = t0 * t0 + t1 * t1 + t2 * t2 + t3 * t3;
    __shared__ float r1[256], r2[256];
    r1[tid] = s; r2[tid] = ss; __syncthreads();
    #pragma unroll
    for (int o = 128; o > 0; o >>= 1) {
        if (tid < o) { r1[tid] += r1[tid + o]; r2[tid] += r2[tid + o]; }
        __syncthreads();
    }
    float mu  = r1[0] * (1.0f / 1024.0f);
    float var = r2[0] * (1.0f / 1024.0f) - mu * mu;
    float inv = rsqrtf(var + 1e-5f);
    float4 gw = *(const float4*)(lg + c);
    float4 bw = *(const float4*)(lb + c);
    float o0 = (t0 - mu) * inv * gw.x + bw.x;
    float o1 = (t1 - mu) * inv * gw.y + bw.y;
    float o2 = (t2 - mu) * inv * gw.z + bw.z;
    float o3 = (t3 - mu) * inv * gw.w + bw.w;
    float4 hv, lv;
    tf32split(o0, hv.x, lv.x); tf32split(o1, hv.y, lv.y);
    tf32split(o2, hv.z, lv.z); tf32split(o3, hv.w, lv.w);
    *(float4*)(lnh + base) = hv;
    *(float4*)(lnl + base) = lv;
}

__global__ void fc2_sigmoid(const float* __restrict__ h,
                            const float* __restrict__ w,
                            const float* __restrict__ b,
                            float* __restrict__ out) {
    int warp = (blockIdx.x * blockDim.x + threadIdx.x) >> 5;
    int lane = threadIdx.x & 31;
    const float* hr = h + (long long)warp * 512;
    float s = 0.f;
    #pragma unroll
    for (int j = 0; j < 512; j += 32) s += hr[j + lane] * w[j + lane];
    #pragma unroll
    for (int o = 16; o > 0; o >>= 1) s += __shfl_down_sync(0xffffffffu, s, o);
    if (lane == 0) out[warp] = 1.0f / (1.0f + __expf(-(s + b[0])));
}

// ---------------------------------------------------------------------------
extern "C" void kernel_launch(void* const* d_in, const int* in_sizes, int n_in,
                              void* d_out, int out_size) {
    const float* x        = (const float*)d_in[0];
    const float* Wq       = (const float*)d_in[1];
    const float* Wk       = (const float*)d_in[2];
    const float* Wv       = (const float*)d_in[3];
    const float* rel_bias = (const float*)d_in[4];
    const float* conv_w   = (const float*)d_in[5];
    const float* conv_b   = (const float*)d_in[6];
    const float* resg_w   = (const float*)d_in[7];
    const float* resg_b   = (const float*)d_in[8];
    const float* ln_g     = (const float*)d_in[9];
    const float* ln_b     = (const float*)d_in[10];
    const float* fc1_w    = (const float*)d_in[11];
    const float* fc1_b    = (const float*)d_in[12];
    const float* fc2_w    = (const float*)d_in[13];
    const float* fc2_b    = (const float*)d_in[14];
    float* out = (float*)d_out;

    float *xh,*xl,*qh,*ql,*kh,*kl,*vh,*vl,*att,*ph,*pl,*mix,*mh,*ml,*gl;
    float *lnh,*lnl,*hbuf,*wqh,*wql,*wkh,*wkl,*wvh,*wvl,*rgh,*rgl,*f1h,*f1l,*wth,*wtl;
    cudaGetSymbolAddress((void**)&xh,  g_xh);  cudaGetSymbolAddress((void**)&xl,  g_xl);
    cudaGetSymbolAddress((void**)&qh,  g_qh);  cudaGetSymbolAddress((void**)&ql,  g_ql);
    cudaGetSymbolAddress((void**)&kh,  g_kh);  cudaGetSymbolAddress((void**)&kl,  g_kl);
    cudaGetSymbolAddress((void**)&vh,  g_vh);  cudaGetSymbolAddress((void**)&vl,  g_vl);
    cudaGetSymbolAddress((void**)&att, g_att);
    cudaGetSymbolAddress((void**)&ph,  g_ph);  cudaGetSymbolAddress((void**)&pl,  g_pl);
    cudaGetSymbolAddress((void**)&mix, g_mix);
    cudaGetSymbolAddress((void**)&mh,  g_mh);  cudaGetSymbolAddress((void**)&ml,  g_ml);
    cudaGetSymbolAddress((void**)&gl,  g_gl);
    cudaGetSymbolAddress((void**)&lnh, g_lnh); cudaGetSymbolAddress((void**)&lnl, g_lnl);
    cudaGetSymbolAddress((void**)&hbuf,g_h);
    cudaGetSymbolAddress((void**)&wqh, g_wqh); cudaGetSymbolAddress((void**)&wql, g_wql);
    cudaGetSymbolAddress((void**)&wkh, g_wkh); cudaGetSymbolAddress((void**)&wkl, g_wkl);
    cudaGetSymbolAddress((void**)&wvh, g_wvh); cudaGetSymbolAddress((void**)&wvl, g_wvl);
    cudaGetSymbolAddress((void**)&rgh, g_rgh); cudaGetSymbolAddress((void**)&rgl, g_rgl);
    cudaGetSymbolAddress((void**)&f1h, g_f1h); cudaGetSymbolAddress((void**)&f1l, g_f1l);
    cudaGetSymbolAddress((void**)&wth, g_wth); cudaGetSymbolAddress((void**)&wtl, g_wtl);

    // operand splits
    split_arr<<<8192, 256>>>(x, xh, xl, 2097152);
    split_arr<<<1024, 256>>>(Wq, wqh, wql, 262144);
    split_arr<<<1024, 256>>>(Wk, wkh, wkl, 262144);
    split_arr<<<1024, 256>>>(Wv, wvh, wvl, 262144);
    split_arr<<<1024, 256>>>(resg_w, rgh, rgl, 262144);
    split_arr<<<512, 256>>>(fc1_w, f1h, f1l, 131072);
    transpose_w_kernel<<<1024, 256>>>(conv_w, wth, wtl);

    // q/k/v projections (split outputs)
    gemm_tf32_nt<3><<<dim3(8, 64, 1), 256>>>(xh, xl, wqh, wql, qh, ql,
                                             8192, 1024, 1024, nullptr, 1.f, 0, 0, 0);
    gemm_tf32_nt<3><<<dim3(8, 64, 1), 256>>>(xh, xl, wkh, wkl, kh, kl,
                                             8192, 1024, 1024, nullptr, 1.f, 0, 0, 0);
    gemm_tf32_nt<3><<<dim3(8, 64, 1), 256>>>(xh, xl, wvh, wvl, vh, vl,
                                             8192, 1024, 1024, nullptr, 1.f, 0, 0, 0);

    // scores (lower-tri tiles only, batched) -> raw fp32
    gemm_tf32_nt<1><<<dim3(16, 16, 4), 256>>>(qh, ql, kh, kl, att, nullptr,
                                              2048, 2048, 1024, rel_bias, 0.03125f,
                                              2048LL * 1024, 2048LL * 1024,
                                              2048LL * 2048);

    // softmax -> prob hi/lo
    softmax_rows<<<8192, 256>>>(att, ph, pl);

    // att_out = P @ V
    gemm_tf32_pv<<<dim3(8, 16, 4), 256>>>(ph, pl, vh, vl, mix);

    // mix = att_out + conv(v) + conv_b  -> hi/lo
    conv_tf32<<<dim3(8, 16, 4), 256>>>(vh, vl, wth, wtl, conv_b, mix, mh, ml);

    // gate logits
    gemm_tf32_nt<0><<<dim3(8, 64, 1), 256>>>(mh, ml, rgh, rgl, gl, nullptr,
                                             8192, 1024, 1024, nullptr, 1.f, 0, 0, 0);

    // residual gate + layernorm -> hi/lo
    fuse_res_ln<<<8192, 256>>>(x, gl, mh, ml, resg_b, ln_g, ln_b, lnh, lnl);

    // fc1 + gelu
    gemm_tf32_nt<2><<<dim3(4, 64, 1), 256>>>(lnh, lnl, f1h, f1l, hbuf, nullptr,
                                             8192, 512, 1024, fc1_b, 1.f, 0, 0, 0);

    // fc2 + sigmoid
    fc2_sigmoid<<<1024, 256>>>(hbuf, fc2_w, fc2_b, out);
}

// round 13
// speedup vs baseline: 2.2297x; 1.6356x over previous
#include <cuda_runtime.h>
#include <cuda_bf16.h>
#include <math.h>

// ---------------------------------------------------------------------------
// B=4, N=2048, D=1024, GROUPS=4.  All GEMMs via mma.sync m16n8k16 bf16,
// fp32-grade accuracy via bf16 hi/lo 3-product (AhBh + AlBh + AhBl),
// run as 3 sequential K-sections accumulating into the same f32 acc.
// ---------------------------------------------------------------------------
#define PITCHW 136            // words per kp-row (128 + 8 pad)
#define KBOFF  1088           // 8 * PITCHW  (one k16 block)
#define TILE_W 2176           // 2 * KBOFF   (BK=32)

// ------------------------------- scratch -----------------------------------
__device__ __nv_bfloat16 g_xh[8388608],  g_xl[8388608];
__device__ __nv_bfloat16 g_qh[8388608],  g_ql[8388608];
__device__ __nv_bfloat16 g_kh[8388608],  g_kl[8388608];
__device__ __nv_bfloat16 g_vh[8388608],  g_vl[8388608];
__device__ __nv_bfloat16 g_vth[8388608], g_vtl[8388608];   // V^T [b][d][t]
__device__ __nv_bfloat16 g_pbh[16777216], g_pbl[16777216]; // probs hi/lo
__device__ float g_att[16777216];
__device__ float g_mixatt[8388608];
__device__ float g_mixf[8388608];
__device__ __nv_bfloat16 g_mh[8388608], g_ml[8388608];
__device__ float g_gl[8388608];
__device__ __nv_bfloat16 g_lnh[8388608], g_lnl[8388608];
__device__ float g_hbuf[4194304];
__device__ __nv_bfloat16 g_wqh[1048576], g_wql[1048576];
__device__ __nv_bfloat16 g_wkh[1048576], g_wkl[1048576];
__device__ __nv_bfloat16 g_wvh[1048576], g_wvl[1048576];
__device__ __nv_bfloat16 g_rgh[1048576], g_rgl[1048576];
__device__ __nv_bfloat16 g_f1h[524288],  g_f1l[524288];
__device__ __nv_bfloat16 g_wth[786432],  g_wtl[786432];    // conv w [co][tap*256+ci]

// ------------------------------- helpers -----------------------------------
__device__ __forceinline__ unsigned pk2(__nv_bfloat16 a, __nv_bfloat16 b) {
    __nv_bfloat162 t = __halves2bfloat162(a, b);
    return *reinterpret_cast<unsigned*>(&t);
}
__device__ __forceinline__ void bsplit(float v, __nv_bfloat16& h, __nv_bfloat16& l) {
    h = __float2bfloat16(v);
    l = __float2bfloat16(v - __bfloat162float(h));
}
__device__ __forceinline__ void mma16(float* d, const unsigned* a, const unsigned* b) {
    asm("mma.sync.aligned.m16n8k16.row.col.f32.bf16.bf16.f32 "
        "{%0,%1,%2,%3}, {%4,%5,%6,%7}, {%8,%9}, {%0,%1,%2,%3};"
        : "+f"(d[0]), "+f"(d[1]), "+f"(d[2]), "+f"(d[3])
        : "r"(a[0]), "r"(a[1]), "r"(a[2]), "r"(a[3]), "r"(b[0]), "r"(b[1]));
}

// Stash one uint4 (8 bf16 along k, kp rows c8*4..c8*4+3) for dim index r.
// Column is XOR-swizzled by c8 so stores are bank-conflict-free.
__device__ __forceinline__ void stashw(unsigned* t, int r, int c8, uint4 v) {
    unsigned* p = t + ((c8 >> 1) * 8 + (c8 & 1) * 4) * PITCHW + (r ^ (c8 << 3));
    p[0]          = v.x;
    p[PITCHW]     = v.y;
    p[2 * PITCHW] = v.z;
    p[3 * PITCHW] = v.w;
}
// Fragment loads matching the swizzle: kp row kb*8+q has xor (kb<<4);
// kp row kb*8+q+4 has xor (kb<<4)+8.
__device__ __forceinline__ void ldA(const unsigned* s, int kb, int q, int r0,
                                    unsigned* af) {
    int kbo = kb * KBOFF;
    int x0 = kb << 4, x1 = (kb << 4) + 8;
    af[0] = s[kbo + q * PITCHW + (r0 ^ x0)];
    af[1] = s[kbo + q * PITCHW + ((r0 + 8) ^ x0)];
    af[2] = s[kbo + (q + 4) * PITCHW + (r0 ^ x1)];
    af[3] = s[kbo + (q + 4) * PITCHW + ((r0 + 8) ^ x1)];
}
__device__ __forceinline__ void ldB(const unsigned* s, int kb, int q, int c0,
                                    unsigned* bf) {
    int kbo = kb * KBOFF;
    bf[0] = s[kbo + q * PITCHW + (c0 ^ (kb << 4))];
    bf[1] = s[kbo + (q + 4) * PITCHW + (c0 ^ ((kb << 4) + 8))];
}

// ---------------------------------------------------------------------------
// NT GEMM: C = A @ B^T, A:[M,K], B:[N,K] bf16 hi/lo. 3 sequential sections
// (Ah,Bh), (Al,Bh), (Ah,Bl) accumulate into one f32 acc.
// MODE 0 plain f32; 1 scores (scale + bias2d, skip n0>m0, batched);
// MODE 2 fc1 gelu; 3 split bf16 hi/lo.  pvc: causal K bound (Keff=m0+128).
// ---------------------------------------------------------------------------
template<int MODE>
__global__ void __launch_bounds__(256, 2)
gemm_bf16(const __nv_bfloat16* __restrict__ Ah, const __nv_bfloat16* __restrict__ Al,
          const __nv_bfloat16* __restrict__ Bh, const __nv_bfloat16* __restrict__ Bl,
          int N, int K, int pvc,
          long long sA, long long sB, long long sC,
          const float* __restrict__ aux, float scale,
          float* __restrict__ Cf,
          __nv_bfloat16* __restrict__ Ch, __nv_bfloat16* __restrict__ Cl) {
    int m0 = blockIdx.y * 128, n0 = blockIdx.x * 128;
    if (MODE == 1 && n0 > m0) return;
    long long z = blockIdx.z;
    Ah += z * sA; Al += z * sA; Bh += z * sB; Bl += z * sB;
    long long co = z * sC;
    int Keff = pvc ? (m0 + 128) : K;

    __shared__ unsigned sA_[TILE_W], sB_[TILE_W];

    int tid = threadIdx.x, warp = tid >> 5, lane = tid & 31;
    int wm = warp >> 2, wn = warp & 3;
    int g = lane >> 2, q = lane & 3;

    float acc[4][4][4];
    #pragma unroll
    for (int t = 0; t < 4; t++)
        #pragma unroll
        for (int u = 0; u < 4; u++)
            #pragma unroll
            for (int j = 0; j < 4; j++) acc[t][u][j] = 0.f;

    for (int sec = 0; sec < 3; sec++) {
        const __nv_bfloat16* Asec = (sec == 1) ? Al : Ah;
        const __nv_bfloat16* Bsec = (sec == 2) ? Bl : Bh;
        for (int k0 = 0; k0 < Keff; k0 += 32) {
            #pragma unroll
            for (int j = 0; j < 2; j++) {
                int idx = tid + j * 256;
                int r = idx >> 2, c8 = idx & 3;
                int kk = k0 + c8 * 8;
                stashw(sA_, r, c8, *(const uint4*)(Asec + (long long)(m0 + r) * K + kk));
                stashw(sB_, r, c8, *(const uint4*)(Bsec + (long long)(n0 + r) * K + kk));
            }
            __syncthreads();
            #pragma unroll
            for (int kb = 0; kb < 2; kb++) {
                unsigned af[4][4];
                #pragma unroll
                for (int t = 0; t < 4; t++)
                    ldA(sA_, kb, q, wm * 64 + t * 16 + g, af[t]);
                #pragma unroll
                for (int u = 0; u < 4; u++) {
                    unsigned bf[2];
                    ldB(sB_, kb, q, wn * 32 + u * 8 + g, bf);
                    #pragma unroll
                    for (int t = 0; t < 4; t++) mma16(acc[t][u], af[t], bf);
                }
            }
            __syncthreads();
        }
    }

    #pragma unroll
    for (int t = 0; t < 4; t++) {
        #pragma unroll
        for (int u = 0; u < 4; u++) {
            int m = m0 + wm * 64 + t * 16 + g;
            int n = n0 + wn * 32 + u * 8 + q * 2;
            float* a = acc[t][u];
            #pragma unroll
            for (int half = 0; half < 2; half++) {
                int mm = m + half * 8;
                float v0 = a[half * 2], v1 = a[half * 2 + 1];
                long long cof = co + (long long)mm * N + n;
                if (MODE == 0) {
                    *(float2*)(Cf + cof) = make_float2(v0, v1);
                } else if (MODE == 1) {
                    const float* bp = aux + (long long)mm * 2048 + n;
                    *(float2*)(Cf + cof) = make_float2(v0 * scale + bp[0],
                                                       v1 * scale + bp[1]);
                } else if (MODE == 2) {
                    float z0 = v0 + aux[n], z1 = v1 + aux[n + 1];
                    v0 = 0.5f * z0 * (1.f + erff(z0 * 0.70710678118654752f));
                    v1 = 0.5f * z1 * (1.f + erff(z1 * 0.70710678118654752f));
                    *(float2*)(Cf + cof) = make_float2(v0, v1);
                } else {
                    __nv_bfloat16 h0, l0, h1, l1;
                    bsplit(v0, h0, l0);
                    bsplit(v1, h1, l1);
                    *(unsigned*)(Ch + cof) = pk2(h0, h1);
                    *(unsigned*)(Cl + cof) = pk2(l0, l1);
                }
            }
        }
    }
}

// ---------------------------------------------------------------------------
// Grouped conv: NT GEMM over K=768 (tap,ci), A = tap-shifted V (zero-pad).
// Epilogue: Mf = mixatt + acc + cb;  Mh/Ml = bf16 split.
// ---------------------------------------------------------------------------
__global__ void __launch_bounds__(256, 2)
conv_bf16(const __nv_bfloat16* __restrict__ Vh, const __nv_bfloat16* __restrict__ Vl,
          const __nv_bfloat16* __restrict__ Wh, const __nv_bfloat16* __restrict__ Wl,
          const float* __restrict__ mixatt, const float* __restrict__ cb,
          float* __restrict__ Mf, __nv_bfloat16* __restrict__ Mh,
          __nv_bfloat16* __restrict__ Ml) {
    int m0 = blockIdx.y * 128, n0 = blockIdx.x * 128;
    long long b = blockIdx.z;
    int grp = n0 >> 8;
    const __nv_bfloat16* vhb = Vh + b * 2097152 + grp * 256;
    const __nv_bfloat16* vlb = Vl + b * 2097152 + grp * 256;

    __shared__ unsigned sA_[TILE_W], sB_[TILE_W];

    int tid = threadIdx.x, warp = tid >> 5, lane = tid & 31;
    int wm = warp >> 2, wn = warp & 3;
    int g = lane >> 2, q = lane & 3;

    float acc[4][4][4];
    #pragma unroll
    for (int t = 0; t < 4; t++)
        #pragma unroll
        for (int u = 0; u < 4; u++)
            #pragma unroll
            for (int j = 0; j < 4; j++) acc[t][u][j] = 0.f;

    for (int sec = 0; sec < 3; sec++) {
        const __nv_bfloat16* Asec = (sec == 1) ? vlb : vhb;
        const __nv_bfloat16* Bsec = (sec == 2) ? Wl : Wh;
        for (int k0 = 0; k0 < 768; k0 += 32) {
            #pragma unroll
            for (int j = 0; j < 2; j++) {
                int idx = tid + j * 256;
                int r = idx >> 2, c8 = idx & 3;
                int kk = k0 + c8 * 8;
                int tap = kk >> 8, ci = kk & 255;
                int rg = m0 + r + tap - 1;
                uint4 va = make_uint4(0u, 0u, 0u, 0u);
                if (rg >= 0 && rg < 2048)
                    va = *(const uint4*)(Asec + (long long)rg * 1024 + ci);
                stashw(sA_, r, c8, va);
                stashw(sB_, r, c8, *(const uint4*)(Bsec + (long long)(n0 + r) * 768 + kk));
            }
            __syncthreads();
            #pragma unroll
            for (int kb = 0; kb < 2; kb++) {
                unsigned af[4][4];
                #pragma unroll
                for (int t = 0; t < 4; t++)
                    ldA(sA_, kb, q, wm * 64 + t * 16 + g, af[t]);
                #pragma unroll
                for (int u = 0; u < 4; u++) {
                    unsigned bf[2];
                    ldB(sB_, kb, q, wn * 32 + u * 8 + g, bf);
                    #pragma unroll
                    for (int t = 0; t < 4; t++) mma16(acc[t][u], af[t], bf);
                }
            }
            __syncthreads();
        }
    }

    #pragma unroll
    for (int t = 0; t < 4; t++)
        #pragma unroll
        for (int u = 0; u < 4; u++) {
            int m = m0 + wm * 64 + t * 16 + g;
            int n = n0 + wn * 32 + u * 8 + q * 2;
            float* a = acc[t][u];
            #pragma unroll
            for (int half = 0; half < 2; half++) {
                int mm = m + half * 8;
                long long base = (b * 2048 + mm) * 1024 + n;
                float v0 = mixatt[base]     + a[half * 2]     + cb[n];
                float v1 = mixatt[base + 1] + a[half * 2 + 1] + cb[n + 1];
                *(float2*)(Mf + base) = make_float2(v0, v1);
                __nv_bfloat16 h0, l0, h1, l1;
                bsplit(v0, h0, l0);
                bsplit(v1, h1, l1);
                *(unsigned*)(Mh + base) = pk2(h0, h1);
                *(unsigned*)(Ml + base) = pk2(l0, l1);
            }
        }
}

// ------------------------- elementwise / small kernels ----------------------
__global__ void split_bf16(const float* __restrict__ s, __nv_bfloat16* __restrict__ h,
                           __nv_bfloat16* __restrict__ l, int n4) {
    int i = blockIdx.x * blockDim.x + threadIdx.x;
    if (i < n4) {
        float4 v = ((const float4*)s)[i];
        __nv_bfloat16 h0,l0,h1,l1,h2,l2,h3,l3;
        bsplit(v.x,h0,l0); bsplit(v.y,h1,l1); bsplit(v.z,h2,l2); bsplit(v.w,h3,l3);
        ((uint2*)h)[i] = make_uint2(pk2(h0,h1), pk2(h2,h3));
        ((uint2*)l)[i] = make_uint2(pk2(l0,l1), pk2(l2,l3));
    }
}

__global__ void convw_kernel(const float* __restrict__ cw,
                             __nv_bfloat16* __restrict__ wh,
                             __nv_bfloat16* __restrict__ wl) {
    int i = blockIdx.x * blockDim.x + threadIdx.x;
    if (i < 262144) {
        int co = i >> 8, ci = i & 255;
        const float* src = cw + (long long)co * 768 + ci * 3;
        #pragma unroll
        for (int tap = 0; tap < 3; tap++) {
            __nv_bfloat16 h, l;
            bsplit(src[tap], h, l);
            long long o = (long long)co * 768 + tap * 256 + ci;
            wh[o] = h; wl[o] = l;
        }
    }
}

__global__ void transpose_v(const __nv_bfloat16* __restrict__ vh,
                            const __nv_bfloat16* __restrict__ vl,
                            __nv_bfloat16* __restrict__ vth,
                            __nv_bfloat16* __restrict__ vtl) {
    __shared__ __nv_bfloat16 th[32][33], tl[32][33];
    int d0 = blockIdx.x * 32, t0 = blockIdx.y * 32;
    long long b = blockIdx.z;
    int tx = threadIdx.x, ty = threadIdx.y;
    const __nv_bfloat16* ih = vh + b * 2097152;
    const __nv_bfloat16* il = vl + b * 2097152;
    for (int r = ty; r < 32; r += 8) {
        th[r][tx] = ih[(long long)(t0 + r) * 1024 + d0 + tx];
        tl[r][tx] = il[(long long)(t0 + r) * 1024 + d0 + tx];
    }
    __syncthreads();
    __nv_bfloat16* oh = vth + b * 2097152;
    __nv_bfloat16* ol = vtl + b * 2097152;
    for (int r = ty; r < 32; r += 8) {
        oh[(long long)(d0 + r) * 2048 + t0 + tx] = th[tx][r];
        ol[(long long)(d0 + r) * 2048 + t0 + tx] = tl[tx][r];
    }
}

__global__ void softmax_rows(const float* __restrict__ att,
                             __nv_bfloat16* __restrict__ ph,
                             __nv_bfloat16* __restrict__ pl) {
    int row = blockIdx.x;
    int b = row >> 11, i = row & 2047;
    int L = i + 1;
    int Lpad = ((i >> 7) + 1) << 7;
    const float* s = att + ((long long)b * 2048 + i) * 2048;
    __nv_bfloat16* oh = ph + ((long long)b * 2048 + i) * 2048;
    __nv_bfloat16* ol = pl + ((long long)b * 2048 + i) * 2048;
    int tid = threadIdx.x;
    float v[8];
    float m = -3.0e38f;
    #pragma unroll
    for (int r = 0; r < 8; r++) {
        int j = r * 256 + tid;
        v[r] = (j < L) ? s[j] : -3.0e38f;
        m = fmaxf(m, v[r]);
    }
    __shared__ float red[256];
    red[tid] = m; __syncthreads();
    #pragma unroll
    for (int o = 128; o > 0; o >>= 1) {
        if (tid < o) red[tid] = fmaxf(red[tid], red[tid + o]);
        __syncthreads();
    }
    m = red[0]; __syncthreads();
    float sum = 0.f;
    #pragma unroll
    for (int r = 0; r < 8; r++) { v[r] = __expf(v[r] - m); sum += v[r]; }
    red[tid] = sum; __syncthreads();
    #pragma unroll
    for (int o = 128; o > 0; o >>= 1) {
        if (tid < o) red[tid] += red[tid + o];
        __syncthreads();
    }
    float inv = 1.0f / red[0];
    #pragma unroll
    for (int r = 0; r < 8; r++) {
        int j = r * 256 + tid;
        if (j < Lpad) {
            float p = (j < L) ? v[r] * inv : 0.f;
            __nv_bfloat16 h, l;
            bsplit(p, h, l);
            oh[j] = h; ol[j] = l;
        }
    }
}

__global__ void fuse_res_ln(const float* __restrict__ x,
                            const float* __restrict__ gl,
                            const float* __restrict__ mixf,
                            const float* __restrict__ rb,
                            const float* __restrict__ lg,
                            const float* __restrict__ lb,
                            __nv_bfloat16* __restrict__ lnh,
                            __nv_bfloat16* __restrict__ lnl) {
    int row = blockIdx.x;
    int tid = threadIdx.x;
    int c = tid * 4;
    long long base = (long long)row * 1024 + c;
    float4 xv = *(const float4*)(x + base);
    float4 gv = *(const float4*)(gl + base);
    float4 mv = *(const float4*)(mixf + base);
    float4 bv = *(const float4*)(rb + c);
    float t0 = xv.x + mv.x / (1.f + __expf(-(gv.x + bv.x)));
    float t1 = xv.y + mv.y / (1.f + __expf(-(gv.y + bv.y)));
    float t2 = xv.z + mv.z / (1.f + __expf(-(gv.z + bv.z)));
    float t3 = xv.w + mv.w / (1.f + __expf(-(gv.w + bv.w)));
    float s  = t0 + t1 + t2 + t3;
    float ss = t0*t0 + t1*t1 + t2*t2 + t3*t3;
    __shared__ float r1[256], r2[256];
    r1[tid] = s; r2[tid] = ss; __syncthreads();
    #pragma unroll
    for (int o = 128; o > 0; o >>= 1) {
        if (tid < o) { r1[tid] += r1[tid + o]; r2[tid] += r2[tid + o]; }
        __syncthreads();
    }
    float mu  = r1[0] * (1.0f / 1024.0f);
    float var = r2[0] * (1.0f / 1024.0f) - mu * mu;
    float inv = rsqrtf(var + 1e-5f);
    float4 gw = *(const float4*)(lg + c);
    float4 bw = *(const float4*)(lb + c);
    float o0 = (t0 - mu) * inv * gw.x + bw.x;
    float o1 = (t1 - mu) * inv * gw.y + bw.y;
    float o2 = (t2 - mu) * inv * gw.z + bw.z;
    float o3 = (t3 - mu) * inv * gw.w + bw.w;
    __nv_bfloat16 h0,l0,h1,l1,h2,l2,h3,l3;
    bsplit(o0,h0,l0); bsplit(o1,h1,l1); bsplit(o2,h2,l2); bsplit(o3,h3,l3);
    *(uint2*)(lnh + base) = make_uint2(pk2(h0,h1), pk2(h2,h3));
    *(uint2*)(lnl + base) = make_uint2(pk2(l0,l1), pk2(l2,l3));
}

__global__ void fc2_sigmoid(const float* __restrict__ h,
                            const float* __restrict__ w,
                            const float* __restrict__ b,
                            float* __restrict__ out) {
    int warp = (blockIdx.x * blockDim.x + threadIdx.x) >> 5;
    int lane = threadIdx.x & 31;
    const float* hr = h + (long long)warp * 512;
    float s = 0.f;
    #pragma unroll
    for (int j = 0; j < 512; j += 32) s += hr[j + lane] * w[j + lane];
    #pragma unroll
    for (int o = 16; o > 0; o >>= 1) s += __shfl_down_sync(0xffffffffu, s, o);
    if (lane == 0) out[warp] = 1.0f / (1.0f + __expf(-(s + b[0])));
}

// ---------------------------------------------------------------------------
extern "C" void kernel_launch(void* const* d_in, const int* in_sizes, int n_in,
                              void* d_out, int out_size) {
    const float* x        = (const float*)d_in[0];
    const float* Wq       = (const float*)d_in[1];
    const float* Wk       = (const float*)d_in[2];
    const float* Wv       = (const float*)d_in[3];
    const float* rel_bias = (const float*)d_in[4];
    const float* conv_w   = (const float*)d_in[5];
    const float* conv_b   = (const float*)d_in[6];
    const float* resg_w   = (const float*)d_in[7];
    const float* resg_b   = (const float*)d_in[8];
    const float* ln_g     = (const float*)d_in[9];
    const float* ln_b     = (const float*)d_in[10];
    const float* fc1_w    = (const float*)d_in[11];
    const float* fc1_b    = (const float*)d_in[12];
    const float* fc2_w    = (const float*)d_in[13];
    const float* fc2_b    = (const float*)d_in[14];
    float* out = (float*)d_out;

    __nv_bfloat16 *xh,*xl,*qh,*ql,*kh,*kl,*vh,*vl,*vth,*vtl,*pbh,*pbl;
    __nv_bfloat16 *mh,*ml,*lnh,*lnl,*wqh,*wql,*wkh,*wkl,*wvh,*wvl,*rgh,*rgl,*f1h,*f1l,*wth,*wtl;
    float *att,*mixatt,*mixf,*gl,*hbuf;
    cudaGetSymbolAddress((void**)&xh,g_xh);   cudaGetSymbolAddress((void**)&xl,g_xl);
    cudaGetSymbolAddress((void**)&qh,g_qh);   cudaGetSymbolAddress((void**)&ql,g_ql);
    cudaGetSymbolAddress((void**)&kh,g_kh);   cudaGetSymbolAddress((void**)&kl,g_kl);
    cudaGetSymbolAddress((void**)&vh,g_vh);   cudaGetSymbolAddress((void**)&vl,g_vl);
    cudaGetSymbolAddress((void**)&vth,g_vth); cudaGetSymbolAddress((void**)&vtl,g_vtl);
    cudaGetSymbolAddress((void**)&pbh,g_pbh); cudaGetSymbolAddress((void**)&pbl,g_pbl);
    cudaGetSymbolAddress((void**)&att,g_att);
    cudaGetSymbolAddress((void**)&mixatt,g_mixatt);
    cudaGetSymbolAddress((void**)&mixf,g_mixf);
    cudaGetSymbolAddress((void**)&mh,g_mh);   cudaGetSymbolAddress((void**)&ml,g_ml);
    cudaGetSymbolAddress((void**)&gl,g_gl);
    cudaGetSymbolAddress((void**)&lnh,g_lnh); cudaGetSymbolAddress((void**)&lnl,g_lnl);
    cudaGetSymbolAddress((void**)&hbuf,g_hbuf);
    cudaGetSymbolAddress((void**)&wqh,g_wqh); cudaGetSymbolAddress((void**)&wql,g_wql);
    cudaGetSymbolAddress((void**)&wkh,g_wkh); cudaGetSymbolAddress((void**)&wkl,g_wkl);
    cudaGetSymbolAddress((void**)&wvh,g_wvh); cudaGetSymbolAddress((void**)&wvl,g_wvl);
    cudaGetSymbolAddress((void**)&rgh,g_rgh); cudaGetSymbolAddress((void**)&rgl,g_rgl);
    cudaGetSymbolAddress((void**)&f1h,g_f1h); cudaGetSymbolAddress((void**)&f1l,g_f1l);
    cudaGetSymbolAddress((void**)&wth,g_wth); cudaGetSymbolAddress((void**)&wtl,g_wtl);

    // operand splits (one float4 per thread — grids sized to cover FULLY)
    split_bf16<<<8192, 256>>>(x, xh, xl, 2097152);
    split_bf16<<<1024, 256>>>(Wq, wqh, wql, 262144);
    split_bf16<<<1024, 256>>>(Wk, wkh, wkl, 262144);
    split_bf16<<<1024, 256>>>(Wv, wvh, wvl, 262144);
    split_bf16<<<1024, 256>>>(resg_w, rgh, rgl, 262144);
    split_bf16<<<512, 256>>>(fc1_w, f1h, f1l, 131072);
    convw_kernel<<<1024, 256>>>(conv_w, wth, wtl);

    // q/k/v projections (split bf16 outputs)
    gemm_bf16<3><<<dim3(8, 64, 1), 256>>>(xh, xl, wqh, wql, 1024, 1024, 0, 0, 0, 0,
                                          nullptr, 1.f, nullptr, qh, ql);
    gemm_bf16<3><<<dim3(8, 64, 1), 256>>>(xh, xl, wkh, wkl, 1024, 1024, 0, 0, 0, 0,
                                          nullptr, 1.f, nullptr, kh, kl);
    gemm_bf16<3><<<dim3(8, 64, 1), 256>>>(xh, xl, wvh, wvl, 1024, 1024, 0, 0, 0, 0,
                                          nullptr, 1.f, nullptr, vh, vl);

    transpose_v<<<dim3(32, 64, 4), dim3(32, 8)>>>(vh, vl, vth, vtl);

    // scores: att = q@k^T/32 + rel_bias (lower-tri tiles, batched)
    gemm_bf16<1><<<dim3(16, 16, 4), 256>>>(qh, ql, kh, kl, 2048, 1024, 0,
                                           2097152LL, 2097152LL, 4194304LL,
                                           rel_bias, 0.03125f, att, nullptr, nullptr);

    softmax_rows<<<8192, 256>>>(att, pbh, pbl);

    // att_out = P @ V  (B = V^T, causal K bound)
    gemm_bf16<0><<<dim3(8, 16, 4), 256>>>(pbh, pbl, vth, vtl, 1024, 2048, 1,
                                          4194304LL, 2097152LL, 2097152LL,
                                          nullptr, 1.f, mixatt, nullptr, nullptr);

    // mix = att_out + conv(v) + conv_b
    conv_bf16<<<dim3(8, 16, 4), 256>>>(vh, vl, wth, wtl, mixatt, conv_b, mixf, mh, ml);

    // gate logits = mix @ resg_w^T
    gemm_bf16<0><<<dim3(8, 64, 1), 256>>>(mh, ml, rgh, rgl, 1024, 1024, 0, 0, 0, 0,
                                          nullptr, 1.f, gl, nullptr, nullptr);

    fuse_res_ln<<<8192, 256>>>(x, gl, mixf, resg_b, ln_g, ln_b, lnh, lnl);

    // h = gelu(ln @ fc1_w^T + fc1_b)
    gemm_bf16<2><<<dim3(4, 64, 1), 256>>>(lnh, lnl, f1h, f1l, 512, 1024, 0, 0, 0, 0,
                                          fc1_b, 1.f, hbuf, nullptr, nullptr);

    fc2_sigmoid<<<1024, 256>>>(hbuf, fc2_w, fc2_b, out);
}

// round 17
// speedup vs baseline: 3.3231x; 1.4904x over previous
#include <cuda_runtime.h>
#include <cuda_bf16.h>
#include <math.h>

// ---------------------------------------------------------------------------
// B=4, N=2048, D=1024, GROUPS=4.  All GEMMs via mma.sync m16n8k16 bf16,
// fp32-grade accuracy via bf16 hi/lo 3-product (AhBh + AlBh + AhBl),
// FUSED into one K pass: all 4 tiles resident, cp.async double-buffered,
// ldmatrix fragment loads on a 16B-granule XOR-swizzled layout.
// ---------------------------------------------------------------------------

// ------------------------------- scratch -----------------------------------
__device__ __nv_bfloat16 g_xh[8388608],  g_xl[8388608];
__device__ __nv_bfloat16 g_qh[8388608],  g_ql[8388608];
__device__ __nv_bfloat16 g_kh[8388608],  g_kl[8388608];
__device__ __nv_bfloat16 g_vh[8388608],  g_vl[8388608];
__device__ __nv_bfloat16 g_vth[8388608], g_vtl[8388608];   // V^T [b][d][t]
__device__ __nv_bfloat16 g_pbh[16777216], g_pbl[16777216]; // probs hi/lo
__device__ float g_att[16777216];
__device__ float g_mixatt[8388608];
__device__ float g_mixf[8388608];
__device__ __nv_bfloat16 g_mh[8388608], g_ml[8388608];
__device__ float g_gl[8388608];
__device__ __nv_bfloat16 g_lnh[8388608], g_lnl[8388608];
__device__ float g_hbuf[4194304];
__device__ __nv_bfloat16 g_wqh[1048576], g_wql[1048576];
__device__ __nv_bfloat16 g_wkh[1048576], g_wkl[1048576];
__device__ __nv_bfloat16 g_wvh[1048576], g_wvl[1048576];
__device__ __nv_bfloat16 g_rgh[1048576], g_rgl[1048576];
__device__ __nv_bfloat16 g_f1h[524288],  g_f1l[524288];
__device__ __nv_bfloat16 g_wth[786432],  g_wtl[786432];    // conv w [co][tap*256+ci]

// ------------------------------- helpers -----------------------------------
__device__ __forceinline__ unsigned pk2(__nv_bfloat16 a, __nv_bfloat16 b) {
    __nv_bfloat162 t = __halves2bfloat162(a, b);
    return *reinterpret_cast<unsigned*>(&t);
}
__device__ __forceinline__ void bsplit(float v, __nv_bfloat16& h, __nv_bfloat16& l) {
    h = __float2bfloat16(v);
    l = __float2bfloat16(v - __bfloat162float(h));
}
__device__ __forceinline__ void mma16(float* d, const unsigned* a, const unsigned* b) {
    asm("mma.sync.aligned.m16n8k16.row.col.f32.bf16.bf16.f32 "
        "{%0,%1,%2,%3}, {%4,%5,%6,%7}, {%8,%9}, {%0,%1,%2,%3};"
        : "+f"(d[0]), "+f"(d[1]), "+f"(d[2]), "+f"(d[3])
        : "r"(a[0]), "r"(a[1]), "r"(a[2]), "r"(a[3]), "r"(b[0]), "r"(b[1]));
}
__device__ __forceinline__ void cpa16(unsigned dst, const void* src) {
    asm volatile("cp.async.cg.shared.global [%0], [%1], 16;" :: "r"(dst), "l"(src));
}
__device__ __forceinline__ void cpa16z(unsigned dst, const void* src, int sz) {
    asm volatile("cp.async.cg.shared.global [%0], [%1], 16, %2;"
                 :: "r"(dst), "l"(src), "r"(sz));
}
__device__ __forceinline__ void ldsm4(unsigned* r, unsigned addr) {
    asm volatile("ldmatrix.sync.aligned.m8n8.x4.shared.b16 {%0,%1,%2,%3}, [%4];"
                 : "=r"(r[0]), "=r"(r[1]), "=r"(r[2]), "=r"(r[3]) : "r"(addr));
}
#define CP_COMMIT() asm volatile("cp.async.commit_group;")
#define CP_WAIT1()  asm volatile("cp.async.wait_group 1;")

// Tile: 128 rows x 128B (8 granules of 16B): hi at kg 0..3 (k=kg*8..), lo at 4..7.
// Swizzle: physical granule = kg ^ (row & 7)  -> conflict-free STS and ldmatrix.
__device__ __forceinline__ unsigned goff(int row, int kg) {
    return (unsigned)(((row << 3) + (kg ^ (row & 7))) << 4);
}

// ---------------------------------------------------------------------------
// NT GEMM: C = A @ B^T, A:[M,K], B:[N,K] bf16 hi/lo, fused 3-product.
// MODE 0 plain f32; 1 scores (scale+bias2d, skip n0>m0, batched);
// MODE 2 fc1 gelu; 3 split bf16 hi/lo.  pvc: causal K bound (Keff=m0+128).
// Dynamic SMEM 64KB: [Ahl buf0 16K][Bhl buf0 16K][Ahl buf1][Bhl buf1]
// ---------------------------------------------------------------------------
template<int MODE>
__global__ void __launch_bounds__(256, 2)
gemm_bf16(const __nv_bfloat16* __restrict__ Ah, const __nv_bfloat16* __restrict__ Al,
          const __nv_bfloat16* __restrict__ Bh, const __nv_bfloat16* __restrict__ Bl,
          int N, int K, int pvc,
          long long sA, long long sB, long long sC,
          const float* __restrict__ aux, float scale,
          float* __restrict__ Cf,
          __nv_bfloat16* __restrict__ Ch, __nv_bfloat16* __restrict__ Cl) {
    int m0 = blockIdx.y * 128, n0 = blockIdx.x * 128;
    if (MODE == 1 && n0 > m0) return;
    long long z = blockIdx.z;
    Ah += z * sA; Al += z * sA; Bh += z * sB; Bl += z * sB;
    long long co = z * sC;
    int Keff = pvc ? (m0 + 128) : K;
    int niter = Keff >> 5;

    extern __shared__ char dsm[];
    unsigned sb = (unsigned)__cvta_generic_to_shared(dsm);

    int tid = threadIdx.x, warp = tid >> 5, lane = tid & 31;
    int wm = warp >> 2, wn = warp & 3;
    int g = lane >> 2, q = lane & 3;
    int mat = lane >> 3, lrow = lane & 7;
    int rofs = (mat & 1) * 8 + lrow;   // row offset within a 16-row block
    int kgo  = mat >> 1;               // kg offset within a k16 block

    float acc[4][4][4];
    #pragma unroll
    for (int t = 0; t < 4; t++)
        #pragma unroll
        for (int u = 0; u < 4; u++)
            #pragma unroll
            for (int j = 0; j < 4; j++) acc[t][u][j] = 0.f;

    auto fill = [&](int bsel, int k0) {
        unsigned sAb = sb + (unsigned)bsel * 32768u;
        unsigned sBb = sAb + 16384u;
        #pragma unroll
        for (int j = 0; j < 4; j++) {
            int id = tid + j * 256;
            int row = id >> 3, slot = id & 7;
            int k = k0 + (slot & 3) * 8;
            unsigned off = goff(row, slot);
            cpa16(sAb + off, (slot < 4 ? Ah : Al) + (long long)(m0 + row) * K + k);
            cpa16(sBb + off, (slot < 4 ? Bh : Bl) + (long long)(n0 + row) * K + k);
        }
    };

    fill(0, 0);
    CP_COMMIT();
    for (int i = 0; i < niter; i++) {
        if (i + 1 < niter) fill((i + 1) & 1, (i + 1) << 5);
        CP_COMMIT();
        CP_WAIT1();
        __syncthreads();
        unsigned sAb = sb + (unsigned)(i & 1) * 32768u;
        unsigned sBb = sAb + 16384u;
        #pragma unroll
        for (int kb = 0; kb < 2; kb++) {
            int kgb = kb * 2 + kgo;
            unsigned bhv[4][2], blv[4][2];
            #pragma unroll
            for (int p = 0; p < 2; p++) {
                int brow = wn * 32 + p * 16 + rofs;
                unsigned r4[4];
                ldsm4(r4, sBb + goff(brow, kgb));
                bhv[2*p][0]   = r4[0]; bhv[2*p][1]   = r4[2];
                bhv[2*p+1][0] = r4[1]; bhv[2*p+1][1] = r4[3];
                ldsm4(r4, sBb + goff(brow, kgb + 4));
                blv[2*p][0]   = r4[0]; blv[2*p][1]   = r4[2];
                blv[2*p+1][0] = r4[1]; blv[2*p+1][1] = r4[3];
            }
            #pragma unroll
            for (int t = 0; t < 4; t++) {
                int arow = wm * 64 + t * 16 + rofs;
                unsigned ah4[4], al4[4];
                ldsm4(ah4, sAb + goff(arow, kgb));
                ldsm4(al4, sAb + goff(arow, kgb + 4));
                #pragma unroll
                for (int u = 0; u < 4; u++) {
                    mma16(acc[t][u], ah4, bhv[u]);
                    mma16(acc[t][u], al4, bhv[u]);
                    mma16(acc[t][u], ah4, blv[u]);
                }
            }
        }
        __syncthreads();
    }

    #pragma unroll
    for (int t = 0; t < 4; t++) {
        #pragma unroll
        for (int u = 0; u < 4; u++) {
            int m = m0 + wm * 64 + t * 16 + g;
            int n = n0 + wn * 32 + u * 8 + q * 2;
            float* a = acc[t][u];
            #pragma unroll
            for (int half = 0; half < 2; half++) {
                int mm = m + half * 8;
                float v0 = a[half * 2], v1 = a[half * 2 + 1];
                long long cof = co + (long long)mm * N + n;
                if (MODE == 0) {
                    *(float2*)(Cf + cof) = make_float2(v0, v1);
                } else if (MODE == 1) {
                    const float* bp = aux + (long long)mm * 2048 + n;
                    *(float2*)(Cf + cof) = make_float2(v0 * scale + bp[0],
                                                       v1 * scale + bp[1]);
                } else if (MODE == 2) {
                    float z0 = v0 + aux[n], z1 = v1 + aux[n + 1];
                    v0 = 0.5f * z0 * (1.f + erff(z0 * 0.70710678118654752f));
                    v1 = 0.5f * z1 * (1.f + erff(z1 * 0.70710678118654752f));
                    *(float2*)(Cf + cof) = make_float2(v0, v1);
                } else {
                    __nv_bfloat16 h0, l0, h1, l1;
                    bsplit(v0, h0, l0);
                    bsplit(v1, h1, l1);
                    *(unsigned*)(Ch + cof) = pk2(h0, h1);
                    *(unsigned*)(Cl + cof) = pk2(l0, l1);
                }
            }
        }
    }
}

// ---------------------------------------------------------------------------
// Grouped conv: fused 3-product NT GEMM over K=768 (tap,ci), A = shifted V.
// Epilogue: Mf = mixatt + acc + cb;  Mh/Ml = bf16 split.
// ---------------------------------------------------------------------------
__global__ void __launch_bounds__(256, 2)
conv_bf16(const __nv_bfloat16* __restrict__ Vh, const __nv_bfloat16* __restrict__ Vl,
          const __nv_bfloat16* __restrict__ Wh, const __nv_bfloat16* __restrict__ Wl,
          const float* __restrict__ mixatt, const float* __restrict__ cb,
          float* __restrict__ Mf, __nv_bfloat16* __restrict__ Mh,
          __nv_bfloat16* __restrict__ Ml) {
    int m0 = blockIdx.y * 128, n0 = blockIdx.x * 128;
    long long b = blockIdx.z;
    int grp = n0 >> 8;
    const __nv_bfloat16* vhb = Vh + b * 2097152 + grp * 256;
    const __nv_bfloat16* vlb = Vl + b * 2097152 + grp * 256;

    extern __shared__ char dsm[];
    unsigned sb = (unsigned)__cvta_generic_to_shared(dsm);

    int tid = threadIdx.x, warp = tid >> 5, lane = tid & 31;
    int wm = warp >> 2, wn = warp & 3;
    int g = lane >> 2, q = lane & 3;
    int mat = lane >> 3, lrow = lane & 7;
    int rofs = (mat & 1) * 8 + lrow;
    int kgo  = mat >> 1;

    float acc[4][4][4];
    #pragma unroll
    for (int t = 0; t < 4; t++)
        #pragma unroll
        for (int u = 0; u < 4; u++)
            #pragma unroll
            for (int j = 0; j < 4; j++) acc[t][u][j] = 0.f;

    auto fill = [&](int bsel, int k0) {
        unsigned sAb = sb + (unsigned)bsel * 32768u;
        unsigned sBb = sAb + 16384u;
        #pragma unroll
        for (int j = 0; j < 4; j++) {
            int id = tid + j * 256;
            int row = id >> 3, slot = id & 7;
            int k = k0 + (slot & 3) * 8;
            int tap = k >> 8, ci = k & 255;
            int rg = m0 + row + tap - 1;
            int ok = (rg >= 0 && rg < 2048) ? 16 : 0;
            long long sofs = ok ? ((long long)rg * 1024 + ci) : 0;
            unsigned off = goff(row, slot);
            cpa16z(sAb + off, (slot < 4 ? vhb : vlb) + sofs, ok);
            cpa16(sBb + off, (slot < 4 ? Wh : Wl) + (long long)(n0 + row) * 768 + k);
        }
    };

    const int niter = 24;   // 768/32
    fill(0, 0);
    CP_COMMIT();
    for (int i = 0; i < niter; i++) {
        if (i + 1 < niter) fill((i + 1) & 1, (i + 1) << 5);
        CP_COMMIT();
        CP_WAIT1();
        __syncthreads();
        unsigned sAb = sb + (unsigned)(i & 1) * 32768u;
        unsigned sBb = sAb + 16384u;
        #pragma unroll
        for (int kb = 0; kb < 2; kb++) {
            int kgb = kb * 2 + kgo;
            unsigned bhv[4][2], blv[4][2];
            #pragma unroll
            for (int p = 0; p < 2; p++) {
                int brow = wn * 32 + p * 16 + rofs;
                unsigned r4[4];
                ldsm4(r4, sBb + goff(brow, kgb));
                bhv[2*p][0]   = r4[0]; bhv[2*p][1]   = r4[2];
                bhv[2*p+1][0] = r4[1]; bhv[2*p+1][1] = r4[3];
                ldsm4(r4, sBb + goff(brow, kgb + 4));
                blv[2*p][0]   = r4[0]; blv[2*p][1]   = r4[2];
                blv[2*p+1][0] = r4[1]; blv[2*p+1][1] = r4[3];
            }
            #pragma unroll
            for (int t = 0; t < 4; t++) {
                int arow = wm * 64 + t * 16 + rofs;
                unsigned ah4[4], al4[4];
                ldsm4(ah4, sAb + goff(arow, kgb));
                ldsm4(al4, sAb + goff(arow, kgb + 4));
                #pragma unroll
                for (int u = 0; u < 4; u++) {
                    mma16(acc[t][u], ah4, bhv[u]);
                    mma16(acc[t][u], al4, bhv[u]);
                    mma16(acc[t][u], ah4, blv[u]);
                }
            }
        }
        __syncthreads();
    }

    #pragma unroll
    for (int t = 0; t < 4; t++)
        #pragma unroll
        for (int u = 0; u < 4; u++) {
            int m = m0 + wm * 64 + t * 16 + g;
            int n = n0 + wn * 32 + u * 8 + q * 2;
            float* a = acc[t][u];
            #pragma unroll
            for (int half = 0; half < 2; half++) {
                int mm = m + half * 8;
                long long base = (b * 2048 + mm) * 1024 + n;
                float v0 = mixatt[base]     + a[half * 2]     + cb[n];
                float v1 = mixatt[base + 1] + a[half * 2 + 1] + cb[n + 1];
                *(float2*)(Mf + base) = make_float2(v0, v1);
                __nv_bfloat16 h0, l0, h1, l1;
                bsplit(v0, h0, l0);
                bsplit(v1, h1, l1);
                *(unsigned*)(Mh + base) = pk2(h0, h1);
                *(unsigned*)(Ml + base) = pk2(l0, l1);
            }
        }
}

// ------------------------- elementwise / small kernels ----------------------
__global__ void split_bf16(const float* __restrict__ s, __nv_bfloat16* __restrict__ h,
                           __nv_bfloat16* __restrict__ l, int n4) {
    int i = blockIdx.x * blockDim.x + threadIdx.x;
    if (i < n4) {
        float4 v = ((const float4*)s)[i];
        __nv_bfloat16 h0,l0,h1,l1,h2,l2,h3,l3;
        bsplit(v.x,h0,l0); bsplit(v.y,h1,l1); bsplit(v.z,h2,l2); bsplit(v.w,h3,l3);
        ((uint2*)h)[i] = make_uint2(pk2(h0,h1), pk2(h2,h3));
        ((uint2*)l)[i] = make_uint2(pk2(l0,l1), pk2(l2,l3));
    }
}

__global__ void convw_kernel(const float* __restrict__ cw,
                             __nv_bfloat16* __restrict__ wh,
                             __nv_bfloat16* __restrict__ wl) {
    int i = blockIdx.x * blockDim.x + threadIdx.x;
    if (i < 262144) {
        int co = i >> 8, ci = i & 255;
        const float* src = cw + (long long)co * 768 + ci * 3;
        #pragma unroll
        for (int tap = 0; tap < 3; tap++) {
            __nv_bfloat16 h, l;
            bsplit(src[tap], h, l);
            long long o = (long long)co * 768 + tap * 256 + ci;
            wh[o] = h; wl[o] = l;
        }
    }
}

__global__ void transpose_v(const __nv_bfloat16* __restrict__ vh,
                            const __nv_bfloat16* __restrict__ vl,
                            __nv_bfloat16* __restrict__ vth,
                            __nv_bfloat16* __restrict__ vtl) {
    __shared__ __nv_bfloat16 th[32][33], tl[32][33];
    int d0 = blockIdx.x * 32, t0 = blockIdx.y * 32;
    long long b = blockIdx.z;
    int tx = threadIdx.x, ty = threadIdx.y;
    const __nv_bfloat16* ih = vh + b * 2097152;
    const __nv_bfloat16* il = vl + b * 2097152;
    for (int r = ty; r < 32; r += 8) {
        th[r][tx] = ih[(long long)(t0 + r) * 1024 + d0 + tx];
        tl[r][tx] = il[(long long)(t0 + r) * 1024 + d0 + tx];
    }
    __syncthreads();
    __nv_bfloat16* oh = vth + b * 2097152;
    __nv_bfloat16* ol = vtl + b * 2097152;
    for (int r = ty; r < 32; r += 8) {
        oh[(long long)(d0 + r) * 2048 + t0 + tx] = th[tx][r];
        ol[(long long)(d0 + r) * 2048 + t0 + tx] = tl[tx][r];
    }
}

__global__ void softmax_rows(const float* __restrict__ att,
                             __nv_bfloat16* __restrict__ ph,
                             __nv_bfloat16* __restrict__ pl) {
    int row = blockIdx.x;
    int b = row >> 11, i = row & 2047;
    int L = i + 1;
    int Lpad = ((i >> 7) + 1) << 7;
    const float* s = att + ((long long)b * 2048 + i) * 2048;
    __nv_bfloat16* oh = ph + ((long long)b * 2048 + i) * 2048;
    __nv_bfloat16* ol = pl + ((long long)b * 2048 + i) * 2048;
    int tid = threadIdx.x;
    float v[8];
    float m = -3.0e38f;
    #pragma unroll
    for (int r = 0; r < 8; r++) {
        int j = r * 256 + tid;
        v[r] = (j < L) ? s[j] : -3.0e38f;
        m = fmaxf(m, v[r]);
    }
    __shared__ float red[256];
    red[tid] = m; __syncthreads();
    #pragma unroll
    for (int o = 128; o > 0; o >>= 1) {
        if (tid < o) red[tid] = fmaxf(red[tid], red[tid + o]);
        __syncthreads();
    }
    m = red[0]; __syncthreads();
    float sum = 0.f;
    #pragma unroll
    for (int r = 0; r < 8; r++) { v[r] = __expf(v[r] - m); sum += v[r]; }
    red[tid] = sum; __syncthreads();
    #pragma unroll
    for (int o = 128; o > 0; o >>= 1) {
        if (tid < o) red[tid] += red[tid + o];
        __syncthreads();
    }
    float inv = 1.0f / red[0];
    #pragma unroll
    for (int r = 0; r < 8; r++) {
        int j = r * 256 + tid;
        if (j < Lpad) {
            float p = (j < L) ? v[r] * inv : 0.f;
            __nv_bfloat16 h, l;
            bsplit(p, h, l);
            oh[j] = h; ol[j] = l;
        }
    }
}

__global__ void fuse_res_ln(const float* __restrict__ x,
                            const float* __restrict__ gl,
                            const float* __restrict__ mixf,
                            const float* __restrict__ rb,
                            const float* __restrict__ lg,
                            const float* __restrict__ lb,
                            __nv_bfloat16* __restrict__ lnh,
                            __nv_bfloat16* __restrict__ lnl) {
    int row = blockIdx.x;
    int tid = threadIdx.x;
    int c = tid * 4;
    long long base = (long long)row * 1024 + c;
    float4 xv = *(const float4*)(x + base);
    float4 gv = *(const float4*)(gl + base);
    float4 mv = *(const float4*)(mixf + base);
    float4 bv = *(const float4*)(rb + c);
    float t0 = xv.x + mv.x / (1.f + __expf(-(gv.x + bv.x)));
    float t1 = xv.y + mv.y / (1.f + __expf(-(gv.y + bv.y)));
    float t2 = xv.z + mv.z / (1.f + __expf(-(gv.z + bv.z)));
    float t3 = xv.w + mv.w / (1.f + __expf(-(gv.w + bv.w)));
    float s  = t0 + t1 + t2 + t3;
    float ss = t0*t0 + t1*t1 + t2*t2 + t3*t3;
    __shared__ float r1[256], r2[256];
    r1[tid] = s; r2[tid] = ss; __syncthreads();
    #pragma unroll
    for (int o = 128; o > 0; o >>= 1) {
        if (tid < o) { r1[tid] += r1[tid + o]; r2[tid] += r2[tid + o]; }
        __syncthreads();
    }
    float mu  = r1[0] * (1.0f / 1024.0f);
    float var = r2[0] * (1.0f / 1024.0f) - mu * mu;
    float inv = rsqrtf(var + 1e-5f);
    float4 gw = *(const float4*)(lg + c);
    float4 bw = *(const float4*)(lb + c);
    float o0 = (t0 - mu) * inv * gw.x + bw.x;
    float o1 = (t1 - mu) * inv * gw.y + bw.y;
    float o2 = (t2 - mu) * inv * gw.z + bw.z;
    float o3 = (t3 - mu) * inv * gw.w + bw.w;
    __nv_bfloat16 h0,l0,h1,l1,h2,l2,h3,l3;
    bsplit(o0,h0,l0); bsplit(o1,h1,l1); bsplit(o2,h2,l2); bsplit(o3,h3,l3);
    *(uint2*)(lnh + base) = make_uint2(pk2(h0,h1), pk2(h2,h3));
    *(uint2*)(lnl + base) = make_uint2(pk2(l0,l1), pk2(l2,l3));
}

__global__ void fc2_sigmoid(const float* __restrict__ h,
                            const float* __restrict__ w,
                            const float* __restrict__ b,
                            float* __restrict__ out) {
    int warp = (blockIdx.x * blockDim.x + threadIdx.x) >> 5;
    int lane = threadIdx.x & 31;
    const float* hr = h + (long long)warp * 512;
    float s = 0.f;
    #pragma unroll
    for (int j = 0; j < 512; j += 32) s += hr[j + lane] * w[j + lane];
    #pragma unroll
    for (int o = 16; o > 0; o >>= 1) s += __shfl_down_sync(0xffffffffu, s, o);
    if (lane == 0) out[warp] = 1.0f / (1.0f + __expf(-(s + b[0])));
}

// ---------------------------------------------------------------------------
extern "C" void kernel_launch(void* const* d_in, const int* in_sizes, int n_in,
                              void* d_out, int out_size) {
    const float* x        = (const float*)d_in[0];
    const float* Wq       = (const float*)d_in[1];
    const float* Wk       = (const float*)d_in[2];
    const float* Wv       = (const float*)d_in[3];
    const float* rel_bias = (const float*)d_in[4];
    const float* conv_w   = (const float*)d_in[5];
    const float* conv_b   = (const float*)d_in[6];
    const float* resg_w   = (const float*)d_in[7];
    const float* resg_b   = (const float*)d_in[8];
    const float* ln_g     = (const float*)d_in[9];
    const float* ln_b     = (const float*)d_in[10];
    const float* fc1_w    = (const float*)d_in[11];
    const float* fc1_b    = (const float*)d_in[12];
    const float* fc2_w    = (const float*)d_in[13];
    const float* fc2_b    = (const float*)d_in[14];
    float* out = (float*)d_out;

    __nv_bfloat16 *xh,*xl,*qh,*ql,*kh,*kl,*vh,*vl,*vth,*vtl,*pbh,*pbl;
    __nv_bfloat16 *mh,*ml,*lnh,*lnl,*wqh,*wql,*wkh,*wkl,*wvh,*wvl,*rgh,*rgl,*f1h,*f1l,*wth,*wtl;
    float *att,*mixatt,*mixf,*gl,*hbuf;
    cudaGetSymbolAddress((void**)&xh,g_xh);   cudaGetSymbolAddress((void**)&xl,g_xl);
    cudaGetSymbolAddress((void**)&qh,g_qh);   cudaGetSymbolAddress((void**)&ql,g_ql);
    cudaGetSymbolAddress((void**)&kh,g_kh);   cudaGetSymbolAddress((void**)&kl,g_kl);
    cudaGetSymbolAddress((void**)&vh,g_vh);   cudaGetSymbolAddress((void**)&vl,g_vl);
    cudaGetSymbolAddress((void**)&vth,g_vth); cudaGetSymbolAddress((void**)&vtl,g_vtl);
    cudaGetSymbolAddress((void**)&pbh,g_pbh); cudaGetSymbolAddress((void**)&pbl,g_pbl);
    cudaGetSymbolAddress((void**)&att,g_att);
    cudaGetSymbolAddress((void**)&mixatt,g_mixatt);
    cudaGetSymbolAddress((void**)&mixf,g_mixf);
    cudaGetSymbolAddress((void**)&mh,g_mh);   cudaGetSymbolAddress((void**)&ml,g_ml);
    cudaGetSymbolAddress((void**)&gl,g_gl);
    cudaGetSymbolAddress((void**)&lnh,g_lnh); cudaGetSymbolAddress((void**)&lnl,g_lnl);
    cudaGetSymbolAddress((void**)&hbuf,g_hbuf);
    cudaGetSymbolAddress((void**)&wqh,g_wqh); cudaGetSymbolAddress((void**)&wql,g_wql);
    cudaGetSymbolAddress((void**)&wkh,g_wkh); cudaGetSymbolAddress((void**)&wkl,g_wkl);
    cudaGetSymbolAddress((void**)&wvh,g_wvh); cudaGetSymbolAddress((void**)&wvl,g_wvl);
    cudaGetSymbolAddress((void**)&rgh,g_rgh); cudaGetSymbolAddress((void**)&rgl,g_rgl);
    cudaGetSymbolAddress((void**)&f1h,g_f1h); cudaGetSymbolAddress((void**)&f1l,g_f1l);
    cudaGetSymbolAddress((void**)&wth,g_wth); cudaGetSymbolAddress((void**)&wtl,g_wtl);

    const int DSM = 65536;
    cudaFuncSetAttribute(gemm_bf16<0>, cudaFuncAttributeMaxDynamicSharedMemorySize, DSM);
    cudaFuncSetAttribute(gemm_bf16<1>, cudaFuncAttributeMaxDynamicSharedMemorySize, DSM);
    cudaFuncSetAttribute(gemm_bf16<2>, cudaFuncAttributeMaxDynamicSharedMemorySize, DSM);
    cudaFuncSetAttribute(gemm_bf16<3>, cudaFuncAttributeMaxDynamicSharedMemorySize, DSM);
    cudaFuncSetAttribute(conv_bf16,    cudaFuncAttributeMaxDynamicSharedMemorySize, DSM);

    // operand splits
    split_bf16<<<8192, 256>>>(x, xh, xl, 2097152);
    split_bf16<<<1024, 256>>>(Wq, wqh, wql, 262144);
    split_bf16<<<1024, 256>>>(Wk, wkh, wkl, 262144);
    split_bf16<<<1024, 256>>>(Wv, wvh, wvl, 262144);
    split_bf16<<<1024, 256>>>(resg_w, rgh, rgl, 262144);
    split_bf16<<<512, 256>>>(fc1_w, f1h, f1l, 131072);
    convw_kernel<<<1024, 256>>>(conv_w, wth, wtl);

    // q/k/v projections (split bf16 outputs)
    gemm_bf16<3><<<dim3(8, 64, 1), 256, DSM>>>(xh, xl, wqh, wql, 1024, 1024, 0, 0, 0, 0,
                                               nullptr, 1.f, nullptr, qh, ql);
    gemm_bf16<3><<<dim3(8, 64, 1), 256, DSM>>>(xh, xl, wkh, wkl, 1024, 1024, 0, 0, 0, 0,
                                               nullptr, 1.f, nullptr, kh, kl);
    gemm_bf16<3><<<dim3(8, 64, 1), 256, DSM>>>(xh, xl, wvh, wvl, 1024, 1024, 0, 0, 0, 0,
                                               nullptr, 1.f, nullptr, vh, vl);

    transpose_v<<<dim3(32, 64, 4), dim3(32, 8)>>>(vh, vl, vth, vtl);

    // scores: att = q@k^T/32 + rel_bias (lower-tri tiles, batched)
    gemm_bf16<1><<<dim3(16, 16, 4), 256, DSM>>>(qh, ql, kh, kl, 2048, 1024, 0,
                                                2097152LL, 2097152LL, 4194304LL,
                                                rel_bias, 0.03125f, att, nullptr, nullptr);

    softmax_rows<<<8192, 256>>>(att, pbh, pbl);

    // att_out = P @ V  (B = V^T, causal K bound)
    gemm_bf16<0><<<dim3(8, 16, 4), 256, DSM>>>(pbh, pbl, vth, vtl, 1024, 2048, 1,
                                               4194304LL, 2097152LL, 2097152LL,
                                               nullptr, 1.f, mixatt, nullptr, nullptr);

    // mix = att_out + conv(v) + conv_b
    conv_bf16<<<dim3(8, 16, 4), 256, DSM>>>(vh, vl, wth, wtl, mixatt, conv_b, mixf, mh, ml);

    // gate logits = mix @ resg_w^T
    gemm_bf16<0><<<dim3(8, 64, 1), 256, DSM>>>(mh, ml, rgh, rgl, 1024, 1024, 0, 0, 0, 0,
                                               nullptr, 1.f, gl, nullptr, nullptr);

    fuse_res_ln<<<8192, 256>>>(x, gl, mixf, resg_b, ln_g, ln_b, lnh, lnl);

    // h = gelu(ln @ fc1_w^T + fc1_b)
    gemm_bf16<2><<<dim3(4, 64, 1), 256, DSM>>>(lnh, lnl, f1h, f1l, 512, 1024, 0, 0, 0, 0,
                                               fc1_b, 1.f, hbuf, nullptr, nullptr);

    fc2_sigmoid<<<1024, 256>>>(hbuf, fc2_w, fc2_b, out);
}